// round 2
// baseline (speedup 1.0000x reference)
#include <cuda_runtime.h>
#include <math.h>

#define BSZ  16
#define CDIM 384
#define LDIM 4096
#define PDIM 192
#define BLTOK (BSZ*LDIM)      // 65536
#define NCH  64
#define TCH  64

// ---------------- static scratch (no allocations allowed) ----------------
__device__ float g_fx[(size_t)BLTOK*CDIM];
__device__ float g_bu[(size_t)BLTOK*CDIM];   // packed: cols [0,192)=re, [192,384)=im ; becomes xs after scan
__device__ float g_y [(size_t)BLTOK*CDIM];
__device__ float g_fy[(size_t)BLTOK*CDIM];
__device__ float g_z [(size_t)BLTOK*2*CDIM];
__device__ float g_gg[(size_t)BLTOK*CDIM];
__device__ float g_wb[CDIM*CDIM];            // packed B_bar  [2P, C]
__device__ float g_wc[CDIM*CDIM];            // packed C_eff  [C, 2P]
__device__ float g_lam [2*PDIM];             // lam_bar (re,im)
__device__ float g_lamT[2*PDIM];             // lam_bar^TCH
__device__ float g_carry[(size_t)BSZ*NCH*CDIM];

__device__ __forceinline__ float gelu_f(float v){
    return 0.5f*v*(1.0f + erff(v*0.70710678118654752f));
}

// ---------------- prep: discretization ----------------
__global__ void prep_lam(const float* __restrict__ Lam, const float* __restrict__ logstep){
    int p = threadIdx.x;
    float step = expf(logstep[p]);
    float lre = Lam[2*p], lim = Lam[2*p+1];
    double a  = exp((double)lre*(double)step);
    double th = (double)lim*(double)step;
    g_lam[2*p]   = (float)(a*cos(th));
    g_lam[2*p+1] = (float)(a*sin(th));
    double aT  = exp((double)TCH*(double)lre*(double)step);
    double thT = (double)TCH*th;
    g_lamT[2*p]   = (float)(aT*cos(thT));
    g_lamT[2*p+1] = (float)(aT*sin(thT));
}

// B_bar = ((lam_bar-1)/lam) * Bc ; rows [0,P)=re, [P,2P)=im
__global__ void prep_wb(const float* __restrict__ Lam, const float* __restrict__ Bmat){
    int p = blockIdx.x, c = threadIdx.x;
    float lre = Lam[2*p], lim = Lam[2*p+1];
    float lbr = g_lam[2*p], lbi = g_lam[2*p+1];
    float den = lre*lre + lim*lim;
    float cr = ((lbr-1.0f)*lre + lbi*lim)/den;
    float ci = (lbi*lre - (lbr-1.0f)*lim)/den;
    float br = Bmat[(p*CDIM + c)*2], bi = Bmat[(p*CDIM + c)*2 + 1];
    g_wb[(size_t)p*CDIM + c]        = cr*br - ci*bi;
    g_wb[(size_t)(PDIM+p)*CDIM + c] = cr*bi + ci*br;
}

// C_eff[h, p] = 2*mask*C_re ; C_eff[h, P+p] = -2*mask*C_im  (so y_pre = xs_packed @ C_eff^T = 2*Re(C xs))
__global__ void prep_wc(const float* __restrict__ Lam, const float* __restrict__ logstep,
                        const float* __restrict__ Cmat){
    int h = blockIdx.x, p = threadIdx.x;
    float step = expf(logstep[p]);
    float lim = Lam[2*p+1];
    float freq = step*fabsf(lim)*(float)(1.0/(2.0*3.14159265358979323846));
    float m = (freq < 0.25f) ? 2.0f : 0.0f;
    float cre = Cmat[(h*PDIM + p)*2], cim = Cmat[(h*PDIM + p)*2 + 1];
    g_wc[(size_t)h*CDIM + p]        =  m*cre;
    g_wc[(size_t)h*CDIM + PDIM + p] = -m*cim;
}

// ---------------- LayerNorm 1 : x[B,C,L] (transposed read) -> fx[BL,C] ----------------
__global__ __launch_bounds__(256) void ln1_kernel(const float* __restrict__ x,
                                                  const float* __restrict__ gam,
                                                  const float* __restrict__ bet,
                                                  float* __restrict__ fx){
    __shared__ float tile[CDIM][17];
    int b = blockIdx.y, l0 = blockIdx.x*16;
    int tid = threadIdx.x;
    for (int idx = tid; idx < CDIM*16; idx += 256){
        int c = idx >> 4, j = idx & 15;
        tile[c][j] = x[((size_t)b*CDIM + c)*LDIM + l0 + j];
    }
    __syncthreads();
    int w = tid >> 5, lane = tid & 31;
    for (int j = w*2; j < w*2 + 2; j++){
        float v[12]; float s = 0.0f;
        #pragma unroll
        for (int k = 0; k < 12; k++){ v[k] = tile[lane + 32*k][j]; s += v[k]; }
        #pragma unroll
        for (int o = 16; o; o >>= 1) s += __shfl_xor_sync(0xffffffffu, s, o);
        float mu = s * (1.0f/CDIM);
        float q = 0.0f;
        #pragma unroll
        for (int k = 0; k < 12; k++){ float d = v[k]-mu; q += d*d; }
        #pragma unroll
        for (int o = 16; o; o >>= 1) q += __shfl_xor_sync(0xffffffffu, q, o);
        float inv = rsqrtf(q*(1.0f/CDIM) + 1e-5f);
        size_t row = ((size_t)b*LDIM + l0 + j)*CDIM;
        #pragma unroll
        for (int k = 0; k < 12; k++){
            int c = lane + 32*k;
            fx[row + c] = (v[k]-mu)*inv*gam[c] + bet[c];
        }
    }
}

// ---------------- LayerNorm 2 : y[BL,C] -> fy[BL,C] ----------------
__global__ __launch_bounds__(256) void ln2_kernel(const float* __restrict__ y,
                                                  const float* __restrict__ gam,
                                                  const float* __restrict__ bet,
                                                  float* __restrict__ fy){
    int row  = blockIdx.x*8 + (threadIdx.x >> 5);
    int lane = threadIdx.x & 31;
    const float4* r4 = (const float4*)(y + (size_t)row*CDIM);
    float4 v[3]; float s = 0.0f;
    #pragma unroll
    for (int k = 0; k < 3; k++){ v[k] = r4[lane + 32*k]; s += v[k].x+v[k].y+v[k].z+v[k].w; }
    #pragma unroll
    for (int o = 16; o; o >>= 1) s += __shfl_xor_sync(0xffffffffu, s, o);
    float mu = s * (1.0f/CDIM);
    float q = 0.0f;
    #pragma unroll
    for (int k = 0; k < 3; k++){
        float dx=v[k].x-mu, dy=v[k].y-mu, dz=v[k].z-mu, dw=v[k].w-mu;
        q += dx*dx+dy*dy+dz*dz+dw*dw;
    }
    #pragma unroll
    for (int o = 16; o; o >>= 1) q += __shfl_xor_sync(0xffffffffu, q, o);
    float inv = rsqrtf(q*(1.0f/CDIM) + 1e-5f);
    float4* o4 = (float4*)(fy + (size_t)row*CDIM);
    const float4* g4 = (const float4*)gam;
    const float4* b4 = (const float4*)bet;
    #pragma unroll
    for (int k = 0; k < 3; k++){
        int c4 = lane + 32*k;
        float4 gg = g4[c4], bb = b4[c4], r;
        r.x = (v[k].x-mu)*inv*gg.x + bb.x;
        r.y = (v[k].y-mu)*inv*gg.y + bb.y;
        r.z = (v[k].z-mu)*inv*gg.z + bb.z;
        r.w = (v[k].w-mu)*inv*gg.w + bb.w;
        o4[c4] = r;
    }
}

// ---------------- SGEMM NT: C[M,N] = A[M,K] @ B[N,K]^T, fused epilogues ----------------
// EPI 0: plain   EPI 1: v=acc+D[n]*fx; out=gelu(v)+fx   EPI 2: out=acc+e0
template<int EPI>
__global__ __launch_bounds__(256,2) void sgemm_nt(const float* __restrict__ A,
                                                  const float* __restrict__ Bm,
                                                  float* __restrict__ Cout,
                                                  int N, int K,
                                                  const float* __restrict__ e0,
                                                  const float* __restrict__ e1){
    __shared__ float As[16][128];
    __shared__ float Bs[16][128];
    int bm = blockIdx.y*128, bn = blockIdx.x*128;
    int tid = threadIdx.x;
    int tr = tid >> 4, tc = tid & 15;
    float acc[8][8] = {};
    const float* Ab = A  + (size_t)bm*K;
    const float* Bb = Bm + (size_t)bn*K;
    for (int k0 = 0; k0 < K; k0 += 16){
        #pragma unroll
        for (int i = 0; i < 2; i++){
            int lin = tid + i*256;
            int row = lin >> 2;
            int kc  = (lin & 3) << 2;
            float4 va = *(const float4*)(Ab + (size_t)row*K + k0 + kc);
            As[kc][row]=va.x; As[kc+1][row]=va.y; As[kc+2][row]=va.z; As[kc+3][row]=va.w;
            float4 vb = *(const float4*)(Bb + (size_t)row*K + k0 + kc);
            Bs[kc][row]=vb.x; Bs[kc+1][row]=vb.y; Bs[kc+2][row]=vb.z; Bs[kc+3][row]=vb.w;
        }
        __syncthreads();
        #pragma unroll
        for (int k = 0; k < 16; k++){
            float a[8], b[8];
            *(float4*)&a[0] = *(const float4*)&As[k][tr*8];
            *(float4*)&a[4] = *(const float4*)&As[k][tr*8+4];
            *(float4*)&b[0] = *(const float4*)&Bs[k][tc*8];
            *(float4*)&b[4] = *(const float4*)&Bs[k][tc*8+4];
            #pragma unroll
            for (int i = 0; i < 8; i++)
                #pragma unroll
                for (int j = 0; j < 8; j++)
                    acc[i][j] = fmaf(a[i], b[j], acc[i][j]);
        }
        __syncthreads();
    }
    #pragma unroll
    for (int i = 0; i < 8; i++){
        size_t m = (size_t)bm + tr*8 + i;
        float* outp = Cout + m*(size_t)N + bn + tc*8;
        float o[8];
        if (EPI == 0){
            #pragma unroll
            for (int j = 0; j < 8; j++) o[j] = acc[i][j];
        } else {
            const float* ep = e0 + m*(size_t)CDIM + bn + tc*8;
            float f[8];
            *(float4*)&f[0] = *(const float4*)ep;
            *(float4*)&f[4] = *(const float4*)(ep+4);
            if (EPI == 1){
                #pragma unroll
                for (int j = 0; j < 8; j++){
                    float v = acc[i][j] + e1[bn + tc*8 + j]*f[j];
                    o[j] = gelu_f(v) + f[j];
                }
            } else {
                #pragma unroll
                for (int j = 0; j < 8; j++) o[j] = acc[i][j] + f[j];
            }
        }
        *(float4*)&outp[0] = *(float4*)&o[0];
        *(float4*)&outp[4] = *(float4*)&o[4];
    }
}

// ---------------- chunked constant-coefficient complex scan ----------------
__global__ void scan_a(float* __restrict__ bu, float* __restrict__ carry){
    int p = threadIdx.x, ch = blockIdx.x, b = blockIdx.y;
    float lre = g_lam[2*p], lim = g_lam[2*p+1];
    float sre = 0.0f, sim = 0.0f;
    size_t base = ((size_t)b*LDIM + (size_t)ch*TCH)*CDIM;
    for (int i = 0; i < TCH; i++){
        size_t idx = base + (size_t)i*CDIM;
        float br = bu[idx+p], bi = bu[idx+PDIM+p];
        float nr = fmaf(lre, sre, fmaf(-lim, sim, br));
        float ni = fmaf(lre, sim, fmaf( lim, sre, bi));
        bu[idx+p] = nr; bu[idx+PDIM+p] = ni;
        sre = nr; sim = ni;
    }
    size_t cidx = ((size_t)b*NCH + ch)*CDIM;
    carry[cidx+p] = sre; carry[cidx+PDIM+p] = sim;
}

__global__ void scan_b(float* __restrict__ carry){
    int p = threadIdx.x, b = blockIdx.x;
    float tr = g_lamT[2*p], ti = g_lamT[2*p+1];
    float pr = 0.0f, pi = 0.0f;
    for (int k = 0; k < NCH; k++){
        size_t ci = ((size_t)b*NCH + k)*CDIM;
        float cr = carry[ci+p], cm = carry[ci+PDIM+p];
        carry[ci+p] = pr; carry[ci+PDIM+p] = pi;      // exclusive prefix
        float nr = fmaf(tr, pr, fmaf(-ti, pi, cr));
        float ni = fmaf(tr, pi, fmaf( ti, pr, cm));
        pr = nr; pi = ni;
    }
}

__global__ void scan_c(float* __restrict__ bu, const float* __restrict__ carry){
    int p = threadIdx.x, ch = blockIdx.x, b = blockIdx.y;
    if (ch == 0) return;
    size_t cidx = ((size_t)b*NCH + ch)*CDIM;
    float sre = carry[cidx+p], sim = carry[cidx+PDIM+p];
    float lre = g_lam[2*p], lim = g_lam[2*p+1];
    float pr = lre, pi = lim;                // lam^1
    size_t base = ((size_t)b*LDIM + (size_t)ch*TCH)*CDIM;
    for (int i = 0; i < TCH; i++){
        size_t idx = base + (size_t)i*CDIM;
        bu[idx+p]      += pr*sre - pi*sim;
        bu[idx+PDIM+p] += pr*sim + pi*sre;
        float nr = pr*lre - pi*lim;
        pi = pr*lim + pi*lre;
        pr = nr;
    }
}

// ---------------- GEGLU ----------------
__global__ void geglu_kernel(const float4* __restrict__ z, float4* __restrict__ g){
    int i = blockIdx.x*blockDim.x + threadIdx.x;   // i < BLTOK*96 exactly
    int m = i / 96, h = i - m*96;
    float4 a = z[(size_t)m*192 + h];
    float4 q = z[(size_t)m*192 + 96 + h];
    float4 o;
    o.x = a.x*gelu_f(q.x); o.y = a.y*gelu_f(q.y);
    o.z = a.z*gelu_f(q.z); o.w = a.w*gelu_f(q.w);
    g[i] = o;
}

// ---------------- final transpose [BL,C] -> [B,C,L] ----------------
__global__ void transpose_out(const float* __restrict__ y2, float* __restrict__ out){
    __shared__ float t[32][33];
    int b = blockIdx.z, c0 = blockIdx.y*32, l0 = blockIdx.x*32;
    int tx = threadIdx.x, ty = threadIdx.y;
    for (int i = ty; i < 32; i += 8)
        t[i][tx] = y2[((size_t)b*LDIM + l0 + i)*CDIM + c0 + tx];
    __syncthreads();
    for (int i = ty; i < 32; i += 8)
        out[((size_t)b*CDIM + c0 + i)*LDIM + l0 + tx] = t[tx][i];
}

// ---------------- launch ----------------
extern "C" void kernel_launch(void* const* d_in, const int* in_sizes, int n_in,
                              void* d_out, int out_size){
    const float* x       = (const float*)d_in[0];
    const float* ln1g    = (const float*)d_in[1];
    const float* ln1b    = (const float*)d_in[2];
    const float* Lam     = (const float*)d_in[3];
    const float* Bmat    = (const float*)d_in[4];
    const float* Cmat    = (const float*)d_in[5];
    const float* Dv      = (const float*)d_in[6];
    const float* logstep = (const float*)d_in[7];
    const float* ln2g    = (const float*)d_in[8];
    const float* ln2b    = (const float*)d_in[9];
    const float* Wenc    = (const float*)d_in[10];
    const float* Wdec    = (const float*)d_in[11];
    float* out = (float*)d_out;

    float *fx,*bu,*y,*fy,*z,*gg,*wb,*wc,*carry;
    cudaGetSymbolAddress((void**)&fx,    g_fx);
    cudaGetSymbolAddress((void**)&bu,    g_bu);
    cudaGetSymbolAddress((void**)&y,     g_y);
    cudaGetSymbolAddress((void**)&fy,    g_fy);
    cudaGetSymbolAddress((void**)&z,     g_z);
    cudaGetSymbolAddress((void**)&gg,    g_gg);
    cudaGetSymbolAddress((void**)&wb,    g_wb);
    cudaGetSymbolAddress((void**)&wc,    g_wc);
    cudaGetSymbolAddress((void**)&carry, g_carry);

    prep_lam<<<1, PDIM>>>(Lam, logstep);
    prep_wb<<<PDIM, CDIM>>>(Lam, Bmat);
    prep_wc<<<CDIM, PDIM>>>(Lam, logstep, Cmat);

    ln1_kernel<<<dim3(LDIM/16, BSZ), 256>>>(x, ln1g, ln1b, fx);

    // Bu = fx @ Bbar_packed^T   -> [BL, 2P]
    sgemm_nt<0><<<dim3(3, 512), 256>>>(fx, wb, bu, CDIM, CDIM, nullptr, nullptr);

    scan_a<<<dim3(NCH, BSZ), PDIM>>>(bu, carry);
    scan_b<<<BSZ, PDIM>>>(carry);
    scan_c<<<dim3(NCH, BSZ), PDIM>>>(bu, carry);

    // y = gelu(xs @ Ceff^T + D*fx) + fx
    sgemm_nt<1><<<dim3(3, 512), 256>>>(bu, wc, y, CDIM, CDIM, fx, Dv);

    ln2_kernel<<<BLTOK/8, 256>>>(y, ln2g, ln2b, fy);

    // z = fy @ Wenc^T  -> [BL, 768]
    sgemm_nt<0><<<dim3(6, 512), 256>>>(fy, Wenc, z, 2*CDIM, CDIM, nullptr, nullptr);

    geglu_kernel<<<(BLTOK*96)/256, 256>>>((const float4*)z, (float4*)gg);

    // y2 = gg @ Wdec^T + fy   (reuse g_y)
    sgemm_nt<2><<<dim3(3, 512), 256>>>(gg, Wdec, y, CDIM, CDIM, fy, nullptr);

    transpose_out<<<dim3(LDIM/32, CDIM/32, BSZ), dim3(32, 8)>>>(y, out);
}

// round 4
// speedup vs baseline: 2.2227x; 2.2227x over previous
#include <cuda_runtime.h>
#include <cuda_bf16.h>
#include <math.h>
#include <stdint.h>

#define BSZ  16
#define CDIM 384
#define LDIM 4096
#define PDIM 192
#define BLTOK (BSZ*LDIM)      // 65536
#define NCH  64
#define TCH  64
#define KDIM 384

// ---------------- static scratch (no allocations allowed) ----------------
__device__ float g_fx[(size_t)BLTOK*CDIM];
__device__ float g_bu[(size_t)BLTOK*CDIM];   // packed re/im ; xs after scan (fp32 working)
__device__ float g_y [(size_t)BLTOK*CDIM];
__device__ float g_fy[(size_t)BLTOK*CDIM];
__device__ float g_z [(size_t)BLTOK*2*CDIM];
__device__ float g_lam [2*PDIM];
__device__ float g_lamT[2*PDIM];
__device__ float g_carry[(size_t)BSZ*NCH*CDIM];

// bf16 hi/lo GEMM operands
__device__ __nv_bfloat16 g_fxh[(size_t)BLTOK*CDIM], g_fxl[(size_t)BLTOK*CDIM];
__device__ __nv_bfloat16 g_buh[(size_t)BLTOK*CDIM], g_bul[(size_t)BLTOK*CDIM];
__device__ __nv_bfloat16 g_fyh[(size_t)BLTOK*CDIM], g_fyl[(size_t)BLTOK*CDIM];
__device__ __nv_bfloat16 g_ggh[(size_t)BLTOK*CDIM], g_ggl[(size_t)BLTOK*CDIM];
__device__ __nv_bfloat16 g_wbh[CDIM*CDIM], g_wbl[CDIM*CDIM];
__device__ __nv_bfloat16 g_wch[CDIM*CDIM], g_wcl[CDIM*CDIM];
__device__ __nv_bfloat16 g_weh[2*CDIM*CDIM], g_wel[2*CDIM*CDIM];
__device__ __nv_bfloat16 g_wdh[CDIM*CDIM], g_wdl[CDIM*CDIM];

__device__ __forceinline__ float gelu_f(float v){
    return 0.5f*v*(1.0f + erff(v*0.70710678118654752f));
}
__device__ __forceinline__ void split_hl(float v, __nv_bfloat16& h, __nv_bfloat16& l){
    h = __float2bfloat16(v);
    l = __float2bfloat16(v - __bfloat162float(h));
}
__device__ __forceinline__ uint32_t smem_u32(const void* p){
    uint32_t a;
    asm("{ .reg .u64 t; cvta.to.shared.u64 t, %1; cvt.u32.u64 %0, t; }" : "=r"(a) : "l"(p));
    return a;
}

// ---------------- MMA / ldmatrix / cp.async primitives (sm_80+ neutral PTX) ----------------
#define CP16(sa, ga)  asm volatile("cp.async.cg.shared.global [%0], [%1], 16;" :: "r"(sa), "l"(ga))
#define CPCOMMIT()    asm volatile("cp.async.commit_group;")
#define CPWAIT(n)     asm volatile("cp.async.wait_group %0;" :: "n"(n))

#define LDSM4(r, addr) asm volatile( \
    "ldmatrix.sync.aligned.m8n8.x4.shared.b16 {%0,%1,%2,%3}, [%4];" \
    : "=r"((r)[0]),"=r"((r)[1]),"=r"((r)[2]),"=r"((r)[3]) : "r"(addr))

#define MMA(d, a, b0v, b1v) asm volatile( \
    "mma.sync.aligned.m16n8k16.row.col.f32.bf16.bf16.f32 " \
    "{%0,%1,%2,%3},{%4,%5,%6,%7},{%8,%9},{%0,%1,%2,%3};" \
    : "+f"((d)[0]),"+f"((d)[1]),"+f"((d)[2]),"+f"((d)[3]) \
    : "r"((a)[0]),"r"((a)[1]),"r"((a)[2]),"r"((a)[3]),"r"(b0v),"r"(b1v))

// ============ bf16 hi/lo split NT GEMM: C[M,Nout] = A[M,384] @ B[Nout,384]^T ============
// tile 128x128, BK=32, 2-stage cp.async, warp grid 2x4 (64x32 warp tiles)
// EPI 0: plain   EPI 1: v=acc+e1[n]*e0; out=gelu(v)+e0   EPI 2: out=acc+e0
// SMEM stage: Ahi(0) Alo(10240) Bhi(20480) Blo(30720), row stride 80B, stage 40960B
template<int EPI>
__global__ __launch_bounds__(256,2) void mma_gemm(
    const __nv_bfloat16* __restrict__ Ah, const __nv_bfloat16* __restrict__ Al,
    const __nv_bfloat16* __restrict__ Bh, const __nv_bfloat16* __restrict__ Bl,
    float* __restrict__ Cout, int Nout,
    const float* __restrict__ e0, const float* __restrict__ e1)
{
    extern __shared__ char smem[];
    uint32_t sb = smem_u32(smem);
    const int tid = threadIdx.x;
    const int bm = blockIdx.y*128, bn = blockIdx.x*128;

    // ---- load indexing: 512 x 16B per array per stage; 8 cp.async/thread ----
    const int lr  = tid >> 2;          // row 0..63 (+64 second half)
    const int seg = tid & 3;           // 16B segment within 64B row
    const __nv_bfloat16* pa0h = Ah + (size_t)(bm+lr)*KDIM + seg*8;
    const __nv_bfloat16* pa0l = Al + (size_t)(bm+lr)*KDIM + seg*8;
    const __nv_bfloat16* pb0h = Bh + (size_t)(bn+lr)*KDIM + seg*8;
    const __nv_bfloat16* pb0l = Bl + (size_t)(bn+lr)*KDIM + seg*8;
    const uint32_t s0 = lr*80 + seg*16;

    // ---- compute indexing ----
    const int lane = tid & 31, w = tid >> 5;
    const int wm = (w >> 2)*64, wn = (w & 3)*32;
    const uint32_t aoff = (uint32_t)(wm + (lane & 15))*80 + (lane >> 4)*16;
    const int bg = lane >> 3, blg = lane & 7;
    const uint32_t boff = (uint32_t)(wn + (bg >> 1)*8 + blg)*80 + (bg & 1)*16;

    float acc[4][4][4];
    #pragma unroll
    for (int i=0;i<4;i++)
        #pragma unroll
        for (int j=0;j<4;j++)
            #pragma unroll
            for (int q=0;q<4;q++) acc[i][j][q]=0.f;

    auto issue = [&](int st, int kc){
        uint32_t sbase = sb + st*40960;
        #pragma unroll
        for (int h = 0; h < 2; h++){
            size_t rofs = (size_t)kc + (size_t)h*64*KDIM;
            uint32_t sa = sbase + s0 + h*64*80;
            CP16(sa,         pa0h + rofs);
            CP16(sa + 10240, pa0l + rofs);
            CP16(sa + 20480, pb0h + rofs);
            CP16(sa + 30720, pb0l + rofs);
        }
        CPCOMMIT();
    };

    issue(0, 0);
    for (int c = 0; c < 12; c++){
        if (c < 11){ issue((c+1)&1, (c+1)*32); CPWAIT(1); }
        else       { CPWAIT(0); }
        __syncthreads();
        uint32_t base = sb + (c&1)*40960;
        #pragma unroll
        for (int ks = 0; ks < 2; ks++){
            uint32_t kb = ks*32;   // bytes: 16 bf16
            uint32_t a[4][4], bfh[4][2], bfl[4][2], t[4];
            #pragma unroll
            for (int i=0;i<4;i++) LDSM4(a[i], base + aoff + i*16*80 + kb);          // A hi
            #pragma unroll
            for (int jp=0;jp<2;jp++){
                LDSM4(t, base + 20480 + boff + jp*16*80 + kb);                      // B hi
                bfh[2*jp][0]=t[0]; bfh[2*jp][1]=t[1]; bfh[2*jp+1][0]=t[2]; bfh[2*jp+1][1]=t[3];
                LDSM4(t, base + 30720 + boff + jp*16*80 + kb);                      // B lo
                bfl[2*jp][0]=t[0]; bfl[2*jp][1]=t[1]; bfl[2*jp+1][0]=t[2]; bfl[2*jp+1][1]=t[3];
            }
            #pragma unroll
            for (int i=0;i<4;i++)
                #pragma unroll
                for (int j=0;j<4;j++) MMA(acc[i][j], a[i], bfh[j][0], bfh[j][1]);   // Ahi*Bhi
            #pragma unroll
            for (int i=0;i<4;i++)
                #pragma unroll
                for (int j=0;j<4;j++) MMA(acc[i][j], a[i], bfl[j][0], bfl[j][1]);   // Ahi*Blo
            #pragma unroll
            for (int i=0;i<4;i++) LDSM4(a[i], base + 10240 + aoff + i*16*80 + kb);  // A lo
            #pragma unroll
            for (int i=0;i<4;i++)
                #pragma unroll
                for (int j=0;j<4;j++) MMA(acc[i][j], a[i], bfh[j][0], bfh[j][1]);   // Alo*Bhi
        }
        __syncthreads();
    }

    // ---- epilogue ----
    const int r0 = lane >> 2, cc = (lane & 3)*2;
    #pragma unroll
    for (int i=0;i<4;i++){
        int row = bm + wm + i*16 + r0;
        #pragma unroll
        for (int j=0;j<4;j++){
            int col = bn + wn + j*8 + cc;
            float v0 = acc[i][j][0], v1 = acc[i][j][1];
            float v2 = acc[i][j][2], v3 = acc[i][j][3];
            if (EPI == 1){
                float2 d2 = *(const float2*)(e1 + col);
                float2 f0 = *(const float2*)(e0 + (size_t)row*CDIM + col);
                float2 f1 = *(const float2*)(e0 + (size_t)(row+8)*CDIM + col);
                v0 = gelu_f(v0 + d2.x*f0.x) + f0.x;
                v1 = gelu_f(v1 + d2.y*f0.y) + f0.y;
                v2 = gelu_f(v2 + d2.x*f1.x) + f1.x;
                v3 = gelu_f(v3 + d2.y*f1.y) + f1.y;
            } else if (EPI == 2){
                float2 f0 = *(const float2*)(e0 + (size_t)row*CDIM + col);
                float2 f1 = *(const float2*)(e0 + (size_t)(row+8)*CDIM + col);
                v0 += f0.x; v1 += f0.y; v2 += f1.x; v3 += f1.y;
            }
            *(float2*)(Cout + (size_t)row*Nout + col)     = make_float2(v0, v1);
            *(float2*)(Cout + (size_t)(row+8)*Nout + col) = make_float2(v2, v3);
        }
    }
}

// ---------------- prep: discretization ----------------
__global__ void prep_lam(const float* __restrict__ Lam, const float* __restrict__ logstep){
    int p = threadIdx.x;
    float step = expf(logstep[p]);
    float lre = Lam[2*p], lim = Lam[2*p+1];
    double a  = exp((double)lre*(double)step);
    double th = (double)lim*(double)step;
    g_lam[2*p]   = (float)(a*cos(th));
    g_lam[2*p+1] = (float)(a*sin(th));
    double aT  = exp((double)TCH*(double)lre*(double)step);
    double thT = (double)TCH*th;
    g_lamT[2*p]   = (float)(aT*cos(thT));
    g_lamT[2*p+1] = (float)(aT*sin(thT));
}

__global__ void prep_wb(const float* __restrict__ Lam, const float* __restrict__ Bmat){
    int p = blockIdx.x, c = threadIdx.x;
    float lre = Lam[2*p], lim = Lam[2*p+1];
    float lbr = g_lam[2*p], lbi = g_lam[2*p+1];
    float den = lre*lre + lim*lim;
    float cr = ((lbr-1.0f)*lre + lbi*lim)/den;
    float ci = (lbi*lre - (lbr-1.0f)*lim)/den;
    float br = Bmat[(p*CDIM + c)*2], bi = Bmat[(p*CDIM + c)*2 + 1];
    float vre = cr*br - ci*bi;
    float vim = cr*bi + ci*br;
    __nv_bfloat16 h,l;
    split_hl(vre,h,l); g_wbh[(size_t)p*CDIM + c]=h;        g_wbl[(size_t)p*CDIM + c]=l;
    split_hl(vim,h,l); g_wbh[(size_t)(PDIM+p)*CDIM + c]=h; g_wbl[(size_t)(PDIM+p)*CDIM + c]=l;
}

__global__ void prep_wc(const float* __restrict__ Lam, const float* __restrict__ logstep,
                        const float* __restrict__ Cmat){
    int hrow = blockIdx.x, p = threadIdx.x;
    float step = expf(logstep[p]);
    float lim = Lam[2*p+1];
    float freq = step*fabsf(lim)*(float)(1.0/(2.0*3.14159265358979323846));
    float m = (freq < 0.25f) ? 2.0f : 0.0f;
    float cre = Cmat[(hrow*PDIM + p)*2], cim = Cmat[(hrow*PDIM + p)*2 + 1];
    __nv_bfloat16 h,l;
    split_hl( m*cre,h,l); g_wch[(size_t)hrow*CDIM + p]=h;        g_wcl[(size_t)hrow*CDIM + p]=l;
    split_hl(-m*cim,h,l); g_wch[(size_t)hrow*CDIM + PDIM + p]=h; g_wcl[(size_t)hrow*CDIM + PDIM + p]=l;
}

__global__ void cvt_hl(const float* __restrict__ src, __nv_bfloat16* __restrict__ h,
                       __nv_bfloat16* __restrict__ l, int n){
    int i = blockIdx.x*blockDim.x + threadIdx.x;
    if (i < n){ __nv_bfloat16 hh,ll; split_hl(src[i],hh,ll); h[i]=hh; l[i]=ll; }
}

// ---------------- LayerNorm 1 : x[B,C,L] -> fx fp32 + hi/lo bf16 ----------------
__global__ __launch_bounds__(256) void ln1_kernel(const float* __restrict__ x,
                                                  const float* __restrict__ gam,
                                                  const float* __restrict__ bet,
                                                  float* __restrict__ fx,
                                                  __nv_bfloat16* __restrict__ fxh,
                                                  __nv_bfloat16* __restrict__ fxl){
    __shared__ float tile[CDIM][17];
    int b = blockIdx.y, l0 = blockIdx.x*16;
    int tid = threadIdx.x;
    for (int idx = tid; idx < CDIM*16; idx += 256){
        int c = idx >> 4, j = idx & 15;
        tile[c][j] = x[((size_t)b*CDIM + c)*LDIM + l0 + j];
    }
    __syncthreads();
    int w = tid >> 5, lane = tid & 31;
    for (int j = w*2; j < w*2 + 2; j++){
        float v[12]; float s = 0.0f;
        #pragma unroll
        for (int k = 0; k < 12; k++){ v[k] = tile[lane + 32*k][j]; s += v[k]; }
        #pragma unroll
        for (int o = 16; o; o >>= 1) s += __shfl_xor_sync(0xffffffffu, s, o);
        float mu = s * (1.0f/CDIM);
        float q = 0.0f;
        #pragma unroll
        for (int k = 0; k < 12; k++){ float d = v[k]-mu; q += d*d; }
        #pragma unroll
        for (int o = 16; o; o >>= 1) q += __shfl_xor_sync(0xffffffffu, q, o);
        float inv = rsqrtf(q*(1.0f/CDIM) + 1e-5f);
        size_t row = ((size_t)b*LDIM + l0 + j)*CDIM;
        #pragma unroll
        for (int k = 0; k < 12; k++){
            int c = lane + 32*k;
            float val = (v[k]-mu)*inv*gam[c] + bet[c];
            fx[row + c] = val;
            __nv_bfloat16 h,l; split_hl(val,h,l);
            fxh[row + c] = h; fxl[row + c] = l;
        }
    }
}

// ---------------- LayerNorm 2 : y[BL,C] -> fy fp32 + hi/lo ----------------
__global__ __launch_bounds__(256) void ln2_kernel(const float* __restrict__ y,
                                                  const float* __restrict__ gam,
                                                  const float* __restrict__ bet,
                                                  float* __restrict__ fy,
                                                  __nv_bfloat16* __restrict__ fyh,
                                                  __nv_bfloat16* __restrict__ fyl){
    int row = blockIdx.x*8 + (threadIdx.x >> 5);
    int lane = threadIdx.x & 31;
    const float4* r4 = (const float4*)(y + (size_t)row*CDIM);
    float4 v[3]; float s = 0.0f;
    #pragma unroll
    for (int k = 0; k < 3; k++){ v[k] = r4[lane + 32*k]; s += v[k].x+v[k].y+v[k].z+v[k].w; }
    #pragma unroll
    for (int o = 16; o; o >>= 1) s += __shfl_xor_sync(0xffffffffu, s, o);
    float mu = s * (1.0f/CDIM);
    float q = 0.0f;
    #pragma unroll
    for (int k = 0; k < 3; k++){
        float dx=v[k].x-mu, dy=v[k].y-mu, dz=v[k].z-mu, dw=v[k].w-mu;
        q += dx*dx+dy*dy+dz*dz+dw*dw;
    }
    #pragma unroll
    for (int o = 16; o; o >>= 1) q += __shfl_xor_sync(0xffffffffu, q, o);
    float inv = rsqrtf(q*(1.0f/CDIM) + 1e-5f);
    float4* o4 = (float4*)(fy + (size_t)row*CDIM);
    const float4* g4 = (const float4*)gam;
    const float4* b4 = (const float4*)bet;
    #pragma unroll
    for (int k = 0; k < 3; k++){
        int c4 = lane + 32*k;
        float4 gg = g4[c4], bb = b4[c4], r;
        r.x = (v[k].x-mu)*inv*gg.x + bb.x;
        r.y = (v[k].y-mu)*inv*gg.y + bb.y;
        r.z = (v[k].z-mu)*inv*gg.z + bb.z;
        r.w = (v[k].w-mu)*inv*gg.w + bb.w;
        o4[c4] = r;
        size_t base = (size_t)row*CDIM + c4*4;
        __nv_bfloat16 h,l;
        split_hl(r.x,h,l); fyh[base+0]=h; fyl[base+0]=l;
        split_hl(r.y,h,l); fyh[base+1]=h; fyl[base+1]=l;
        split_hl(r.z,h,l); fyh[base+2]=h; fyl[base+2]=l;
        split_hl(r.w,h,l); fyh[base+3]=h; fyl[base+3]=l;
    }
}

// ---------------- chunked constant-coefficient complex scan ----------------
__global__ void scan_a(float* __restrict__ bu, float* __restrict__ carry){
    int p = threadIdx.x, ch = blockIdx.x, b = blockIdx.y;
    float lre = g_lam[2*p], lim = g_lam[2*p+1];
    float sre = 0.0f, sim = 0.0f;
    size_t base = ((size_t)b*LDIM + (size_t)ch*TCH)*CDIM;
    for (int i = 0; i < TCH; i++){
        size_t idx = base + (size_t)i*CDIM;
        float br = bu[idx+p], bi = bu[idx+PDIM+p];
        float nr = fmaf(lre, sre, fmaf(-lim, sim, br));
        float ni = fmaf(lre, sim, fmaf( lim, sre, bi));
        bu[idx+p] = nr; bu[idx+PDIM+p] = ni;
        sre = nr; sim = ni;
    }
    size_t cidx = ((size_t)b*NCH + ch)*CDIM;
    carry[cidx+p] = sre; carry[cidx+PDIM+p] = sim;
}

__global__ void scan_b(float* __restrict__ carry){
    int p = threadIdx.x, b = blockIdx.x;
    float tr = g_lamT[2*p], ti = g_lamT[2*p+1];
    float pr = 0.0f, pi = 0.0f;
    for (int k = 0; k < NCH; k++){
        size_t ci = ((size_t)b*NCH + k)*CDIM;
        float cr = carry[ci+p], cm = carry[ci+PDIM+p];
        carry[ci+p] = pr; carry[ci+PDIM+p] = pi;
        float nr = fmaf(tr, pr, fmaf(-ti, pi, cr));
        float ni = fmaf(tr, pi, fmaf( ti, pr, cm));
        pr = nr; pi = ni;
    }
}

// scan_c: apply carry (ch>0) and emit xs as bf16 hi/lo
__global__ void scan_c(const float* __restrict__ bu, const float* __restrict__ carry,
                       __nv_bfloat16* __restrict__ bh, __nv_bfloat16* __restrict__ bl){
    int p = threadIdx.x, ch = blockIdx.x, b = blockIdx.y;
    float sre = 0.0f, sim = 0.0f;
    if (ch > 0){
        size_t cidx = ((size_t)b*NCH + ch)*CDIM;
        sre = carry[cidx+p]; sim = carry[cidx+PDIM+p];
    }
    float lre = g_lam[2*p], lim = g_lam[2*p+1];
    float pr = lre, pi = lim;
    size_t base = ((size_t)b*LDIM + (size_t)ch*TCH)*CDIM;
    for (int i = 0; i < TCH; i++){
        size_t idx = base + (size_t)i*CDIM;
        float vr = bu[idx+p]      + (pr*sre - pi*sim);
        float vi = bu[idx+PDIM+p] + (pr*sim + pi*sre);
        float nr = pr*lre - pi*lim;
        pi = pr*lim + pi*lre;
        pr = nr;
        __nv_bfloat16 h,l;
        split_hl(vr,h,l); bh[idx+p]=h;      bl[idx+p]=l;
        split_hl(vi,h,l); bh[idx+PDIM+p]=h; bl[idx+PDIM+p]=l;
    }
}

// ---------------- GEGLU -> bf16 hi/lo ----------------
__global__ void geglu_kernel(const float4* __restrict__ z,
                             __nv_bfloat16* __restrict__ gh,
                             __nv_bfloat16* __restrict__ gl){
    int i = blockIdx.x*blockDim.x + threadIdx.x;   // < BLTOK*96
    int m = i / 96, h = i - m*96;
    float4 a = z[(size_t)m*192 + h];
    float4 q = z[(size_t)m*192 + 96 + h];
    float o0 = a.x*gelu_f(q.x), o1 = a.y*gelu_f(q.y);
    float o2 = a.z*gelu_f(q.z), o3 = a.w*gelu_f(q.w);
    __nv_bfloat16 h0,l0,h1,l1,h2,l2,h3,l3;
    split_hl(o0,h0,l0); split_hl(o1,h1,l1); split_hl(o2,h2,l2); split_hl(o3,h3,l3);
    size_t base = (size_t)i*4;
    *(__nv_bfloat162*)(gh + base)     = __nv_bfloat162(h0,h1);
    *(__nv_bfloat162*)(gh + base + 2) = __nv_bfloat162(h2,h3);
    *(__nv_bfloat162*)(gl + base)     = __nv_bfloat162(l0,l1);
    *(__nv_bfloat162*)(gl + base + 2) = __nv_bfloat162(l2,l3);
}

// ---------------- final transpose [BL,C] -> [B,C,L] ----------------
__global__ void transpose_out(const float* __restrict__ y2, float* __restrict__ out){
    __shared__ float t[32][33];
    int b = blockIdx.z, c0 = blockIdx.y*32, l0 = blockIdx.x*32;
    int tx = threadIdx.x, ty = threadIdx.y;
    for (int i = ty; i < 32; i += 8)
        t[i][tx] = y2[((size_t)b*LDIM + l0 + i)*CDIM + c0 + tx];
    __syncthreads();
    for (int i = ty; i < 32; i += 8)
        out[((size_t)b*CDIM + c0 + i)*LDIM + l0 + tx] = t[tx][i];
}

// ---------------- launch ----------------
extern "C" void kernel_launch(void* const* d_in, const int* in_sizes, int n_in,
                              void* d_out, int out_size){
    const float* x       = (const float*)d_in[0];
    const float* ln1g    = (const float*)d_in[1];
    const float* ln1b    = (const float*)d_in[2];
    const float* Lam     = (const float*)d_in[3];
    const float* Bmat    = (const float*)d_in[4];
    const float* Cmat    = (const float*)d_in[5];
    const float* Dv      = (const float*)d_in[6];
    const float* logstep = (const float*)d_in[7];
    const float* ln2g    = (const float*)d_in[8];
    const float* ln2b    = (const float*)d_in[9];
    const float* Wenc    = (const float*)d_in[10];
    const float* Wdec    = (const float*)d_in[11];
    float* out = (float*)d_out;

    float *fx,*bu,*y,*fy,*z,*carry;
    cudaGetSymbolAddress((void**)&fx,    g_fx);
    cudaGetSymbolAddress((void**)&bu,    g_bu);
    cudaGetSymbolAddress((void**)&y,     g_y);
    cudaGetSymbolAddress((void**)&fy,    g_fy);
    cudaGetSymbolAddress((void**)&z,     g_z);
    cudaGetSymbolAddress((void**)&carry, g_carry);

    __nv_bfloat16 *fxh,*fxl,*buh,*bul,*fyh,*fyl,*ggh,*ggl;
    __nv_bfloat16 *wbh,*wbl,*wch,*wcl,*weh,*wel,*wdh,*wdl;
    cudaGetSymbolAddress((void**)&fxh, g_fxh); cudaGetSymbolAddress((void**)&fxl, g_fxl);
    cudaGetSymbolAddress((void**)&buh, g_buh); cudaGetSymbolAddress((void**)&bul, g_bul);
    cudaGetSymbolAddress((void**)&fyh, g_fyh); cudaGetSymbolAddress((void**)&fyl, g_fyl);
    cudaGetSymbolAddress((void**)&ggh, g_ggh); cudaGetSymbolAddress((void**)&ggl, g_ggl);
    cudaGetSymbolAddress((void**)&wbh, g_wbh); cudaGetSymbolAddress((void**)&wbl, g_wbl);
    cudaGetSymbolAddress((void**)&wch, g_wch); cudaGetSymbolAddress((void**)&wcl, g_wcl);
    cudaGetSymbolAddress((void**)&weh, g_weh); cudaGetSymbolAddress((void**)&wel, g_wel);
    cudaGetSymbolAddress((void**)&wdh, g_wdh); cudaGetSymbolAddress((void**)&wdl, g_wdl);

    const int SMEM_GEMM = 2*40960;   // 80 KB
    cudaFuncSetAttribute(mma_gemm<0>, cudaFuncAttributeMaxDynamicSharedMemorySize, SMEM_GEMM);
    cudaFuncSetAttribute(mma_gemm<1>, cudaFuncAttributeMaxDynamicSharedMemorySize, SMEM_GEMM);
    cudaFuncSetAttribute(mma_gemm<2>, cudaFuncAttributeMaxDynamicSharedMemorySize, SMEM_GEMM);

    prep_lam<<<1, PDIM>>>(Lam, logstep);
    prep_wb<<<PDIM, CDIM>>>(Lam, Bmat);
    prep_wc<<<CDIM, PDIM>>>(Lam, logstep, Cmat);
    cvt_hl<<<(2*CDIM*CDIM + 255)/256, 256>>>(Wenc, weh, wel, 2*CDIM*CDIM);
    cvt_hl<<<(CDIM*CDIM + 255)/256, 256>>>(Wdec, wdh, wdl, CDIM*CDIM);

    ln1_kernel<<<dim3(LDIM/16, BSZ), 256>>>(x, ln1g, ln1b, fx, fxh, fxl);

    // Bu = fx @ Bbar_packed^T   -> [BL, 2P] fp32
    mma_gemm<0><<<dim3(3, 512), 256, SMEM_GEMM>>>(fxh, fxl, wbh, wbl, bu, CDIM, nullptr, nullptr);

    scan_a<<<dim3(NCH, BSZ), PDIM>>>(bu, carry);
    scan_b<<<BSZ, PDIM>>>(carry);
    scan_c<<<dim3(NCH, BSZ), PDIM>>>(bu, carry, buh, bul);

    // y = gelu(xs @ Ceff^T + D*fx) + fx
    mma_gemm<1><<<dim3(3, 512), 256, SMEM_GEMM>>>(buh, bul, wch, wcl, y, CDIM, fx, Dv);

    ln2_kernel<<<BLTOK/8, 256>>>(y, ln2g, ln2b, fy, fyh, fyl);

    // z = fy @ Wenc^T  -> [BL, 768]
    mma_gemm<0><<<dim3(6, 512), 256, SMEM_GEMM>>>(fyh, fyl, weh, wel, z, 2*CDIM, nullptr, nullptr);

    geglu_kernel<<<(BLTOK*96)/256, 256>>>((const float4*)z, ggh, ggl);

    // y2 = gg @ Wdec^T + fy
    mma_gemm<2><<<dim3(3, 512), 256, SMEM_GEMM>>>(ggh, ggl, wdh, wdl, y, CDIM, fy, nullptr);

    transpose_out<<<dim3(LDIM/32, CDIM/32, BSZ), dim3(32, 8)>>>(y, out);
}

// round 5
// speedup vs baseline: 2.2991x; 1.0344x over previous
#include <cuda_runtime.h>
#include <cuda_bf16.h>
#include <math.h>
#include <stdint.h>

#define BSZ  16
#define CDIM 384
#define LDIM 4096
#define PDIM 192
#define BLTOK (BSZ*LDIM)      // 65536
#define NCH  64
#define TCH  64
#define KDIM 384

// ---------------- static scratch (no allocations allowed) ----------------
__device__ float g_bu[(size_t)BLTOK*CDIM];   // Bu fp32 (pre-scan)
__device__ float g_y [(size_t)BLTOK*CDIM];
__device__ float g_lam [2*PDIM];
__device__ float g_lamT[2*PDIM];
__device__ float g_carry[(size_t)BSZ*NCH*CDIM];

// bf16 hi/lo GEMM operands
__device__ __nv_bfloat16 g_fxh[(size_t)BLTOK*CDIM], g_fxl[(size_t)BLTOK*CDIM];
__device__ __nv_bfloat16 g_buh[(size_t)BLTOK*CDIM], g_bul[(size_t)BLTOK*CDIM];
__device__ __nv_bfloat16 g_fyh[(size_t)BLTOK*CDIM], g_fyl[(size_t)BLTOK*CDIM];
__device__ __nv_bfloat16 g_ggh[(size_t)BLTOK*CDIM], g_ggl[(size_t)BLTOK*CDIM];
__device__ __nv_bfloat16 g_wbh[CDIM*CDIM], g_wbl[CDIM*CDIM];
__device__ __nv_bfloat16 g_wch[CDIM*CDIM], g_wcl[CDIM*CDIM];
__device__ __nv_bfloat16 g_weh[2*CDIM*CDIM], g_wel[2*CDIM*CDIM];   // interleaved z1/z2 rows
__device__ __nv_bfloat16 g_wdh[CDIM*CDIM], g_wdl[CDIM*CDIM];

__device__ __forceinline__ float gelu_f(float v){
    return 0.5f*v*(1.0f + erff(v*0.70710678118654752f));
}
__device__ __forceinline__ void split_hl(float v, __nv_bfloat16& h, __nv_bfloat16& l){
    h = __float2bfloat16(v);
    l = __float2bfloat16(v - __bfloat162float(h));
}
__device__ __forceinline__ uint32_t smem_u32(const void* p){
    uint32_t a;
    asm("{ .reg .u64 t; cvta.to.shared.u64 t, %1; cvt.u32.u64 %0, t; }" : "=r"(a) : "l"(p));
    return a;
}

// ---------------- MMA / ldmatrix / cp.async primitives (sm_80+ neutral PTX) ----------------
#define CP16(sa, ga)  asm volatile("cp.async.cg.shared.global [%0], [%1], 16;" :: "r"(sa), "l"(ga))
#define CPCOMMIT()    asm volatile("cp.async.commit_group;")
#define CPWAIT(n)     asm volatile("cp.async.wait_group %0;" :: "n"(n))

#define LDSM4(r, addr) asm volatile( \
    "ldmatrix.sync.aligned.m8n8.x4.shared.b16 {%0,%1,%2,%3}, [%4];" \
    : "=r"((r)[0]),"=r"((r)[1]),"=r"((r)[2]),"=r"((r)[3]) : "r"(addr))

#define MMA(d, a, b0v, b1v) asm volatile( \
    "mma.sync.aligned.m16n8k16.row.col.f32.bf16.bf16.f32 " \
    "{%0,%1,%2,%3},{%4,%5,%6,%7},{%8,%9},{%0,%1,%2,%3};" \
    : "+f"((d)[0]),"+f"((d)[1]),"+f"((d)[2]),"+f"((d)[3]) \
    : "r"((a)[0]),"r"((a)[1]),"r"((a)[2]),"r"((a)[3]),"r"(b0v),"r"(b1v))

// ============ bf16 hi/lo split NT GEMM: C[M,*] = A[M,384] @ B[*,384]^T ============
// tile 128x128, BK=32, 2-stage cp.async, warp grid 2x4 (64x32 warp tiles)
// EPI 0: Cout fp32 plain
// EPI 1: f=e0h+e0l; v=acc+e1[n]*f; Cout=gelu(v)+f   (fp32)
// EPI 3: GEGLU pairs: even/odd cols (z1,z2) -> outH/outL bf16 [BL, 384]
// EPI 4: f=e0h+e0l; o=acc+f; write Cout transposed [B,C,L] via smem staging
template<int EPI>
__global__ __launch_bounds__(256,2) void mma_gemm(
    const __nv_bfloat16* __restrict__ Ah, const __nv_bfloat16* __restrict__ Al,
    const __nv_bfloat16* __restrict__ Bh, const __nv_bfloat16* __restrict__ Bl,
    float* __restrict__ Cout, int Nout,
    __nv_bfloat16* __restrict__ outH, __nv_bfloat16* __restrict__ outL,
    const __nv_bfloat16* __restrict__ e0h, const __nv_bfloat16* __restrict__ e0l,
    const float* __restrict__ e1)
{
    extern __shared__ char smem[];
    uint32_t sb = smem_u32(smem);
    const int tid = threadIdx.x;
    const int bm = blockIdx.y*128, bn = blockIdx.x*128;

    // ---- load indexing: 512 x 16B per array per stage; 8 cp.async/thread ----
    const int lr  = tid >> 2;          // row 0..63 (+64 second half)
    const int seg = tid & 3;           // 16B segment within 64B row
    const __nv_bfloat16* pa0h = Ah + (size_t)(bm+lr)*KDIM + seg*8;
    const __nv_bfloat16* pa0l = Al + (size_t)(bm+lr)*KDIM + seg*8;
    const __nv_bfloat16* pb0h = Bh + (size_t)(bn+lr)*KDIM + seg*8;
    const __nv_bfloat16* pb0l = Bl + (size_t)(bn+lr)*KDIM + seg*8;
    const uint32_t s0 = lr*80 + seg*16;

    // ---- compute indexing ----
    const int lane = tid & 31, w = tid >> 5;
    const int wm = (w >> 2)*64, wn = (w & 3)*32;
    const uint32_t aoff = (uint32_t)(wm + (lane & 15))*80 + (lane >> 4)*16;
    const int bg = lane >> 3, blg = lane & 7;
    const uint32_t boff = (uint32_t)(wn + (bg >> 1)*8 + blg)*80 + (bg & 1)*16;

    float acc[4][4][4];
    #pragma unroll
    for (int i=0;i<4;i++)
        #pragma unroll
        for (int j=0;j<4;j++)
            #pragma unroll
            for (int q=0;q<4;q++) acc[i][j][q]=0.f;

    auto issue = [&](int st, int kc){
        uint32_t sbase = sb + st*40960;
        #pragma unroll
        for (int h = 0; h < 2; h++){
            size_t rofs = (size_t)kc + (size_t)h*64*KDIM;
            uint32_t sa = sbase + s0 + h*64*80;
            CP16(sa,         pa0h + rofs);
            CP16(sa + 10240, pa0l + rofs);
            CP16(sa + 20480, pb0h + rofs);
            CP16(sa + 30720, pb0l + rofs);
        }
        CPCOMMIT();
    };

    issue(0, 0);
    for (int c = 0; c < 12; c++){
        if (c < 11){ issue((c+1)&1, (c+1)*32); CPWAIT(1); }
        else       { CPWAIT(0); }
        __syncthreads();
        uint32_t base = sb + (c&1)*40960;
        #pragma unroll
        for (int ks = 0; ks < 2; ks++){
            uint32_t kb = ks*32;   // bytes: 16 bf16
            uint32_t a[4][4], bfh[4][2], bfl[4][2], t[4];
            #pragma unroll
            for (int i=0;i<4;i++) LDSM4(a[i], base + aoff + i*16*80 + kb);          // A hi
            #pragma unroll
            for (int jp=0;jp<2;jp++){
                LDSM4(t, base + 20480 + boff + jp*16*80 + kb);                      // B hi
                bfh[2*jp][0]=t[0]; bfh[2*jp][1]=t[1]; bfh[2*jp+1][0]=t[2]; bfh[2*jp+1][1]=t[3];
                LDSM4(t, base + 30720 + boff + jp*16*80 + kb);                      // B lo
                bfl[2*jp][0]=t[0]; bfl[2*jp][1]=t[1]; bfl[2*jp+1][0]=t[2]; bfl[2*jp+1][1]=t[3];
            }
            #pragma unroll
            for (int i=0;i<4;i++)
                #pragma unroll
                for (int j=0;j<4;j++) MMA(acc[i][j], a[i], bfh[j][0], bfh[j][1]);   // Ahi*Bhi
            #pragma unroll
            for (int i=0;i<4;i++)
                #pragma unroll
                for (int j=0;j<4;j++) MMA(acc[i][j], a[i], bfl[j][0], bfl[j][1]);   // Ahi*Blo
            #pragma unroll
            for (int i=0;i<4;i++) LDSM4(a[i], base + 10240 + aoff + i*16*80 + kb);  // A lo
            #pragma unroll
            for (int i=0;i<4;i++)
                #pragma unroll
                for (int j=0;j<4;j++) MMA(acc[i][j], a[i], bfh[j][0], bfh[j][1]);   // Alo*Bhi
        }
        __syncthreads();
    }

    // ---- epilogue ----
    const int r0 = lane >> 2, cc = (lane & 3)*2;
    if (EPI == 0 || EPI == 1){
        #pragma unroll
        for (int i=0;i<4;i++){
            int row = bm + wm + i*16 + r0;
            #pragma unroll
            for (int j=0;j<4;j++){
                int col = bn + wn + j*8 + cc;
                float v0 = acc[i][j][0], v1 = acc[i][j][1];
                float v2 = acc[i][j][2], v3 = acc[i][j][3];
                if (EPI == 1){
                    float2 d2 = *(const float2*)(e1 + col);
                    __nv_bfloat162 h0 = *(const __nv_bfloat162*)(e0h + (size_t)row*CDIM + col);
                    __nv_bfloat162 l0 = *(const __nv_bfloat162*)(e0l + (size_t)row*CDIM + col);
                    __nv_bfloat162 h1 = *(const __nv_bfloat162*)(e0h + (size_t)(row+8)*CDIM + col);
                    __nv_bfloat162 l1 = *(const __nv_bfloat162*)(e0l + (size_t)(row+8)*CDIM + col);
                    float f0x = __bfloat162float(h0.x) + __bfloat162float(l0.x);
                    float f0y = __bfloat162float(h0.y) + __bfloat162float(l0.y);
                    float f1x = __bfloat162float(h1.x) + __bfloat162float(l1.x);
                    float f1y = __bfloat162float(h1.y) + __bfloat162float(l1.y);
                    v0 = gelu_f(v0 + d2.x*f0x) + f0x;
                    v1 = gelu_f(v1 + d2.y*f0y) + f0y;
                    v2 = gelu_f(v2 + d2.x*f1x) + f1x;
                    v3 = gelu_f(v3 + d2.y*f1y) + f1y;
                }
                *(float2*)(Cout + (size_t)row*Nout + col)     = make_float2(v0, v1);
                *(float2*)(Cout + (size_t)(row+8)*Nout + col) = make_float2(v2, v3);
            }
        }
    } else if (EPI == 3){
        // GEGLU: even col = z1, odd col = z2 (interleaved W_enc). Output pair index.
        #pragma unroll
        for (int i=0;i<4;i++){
            int row = bm + wm + i*16 + r0;
            #pragma unroll
            for (int j=0;j<4;j++){
                int gcol = (bn >> 1) + (wn >> 1) + j*4 + (lane & 3);
                float g0 = acc[i][j][0] * gelu_f(acc[i][j][1]);
                float g1 = acc[i][j][2] * gelu_f(acc[i][j][3]);
                __nv_bfloat16 h, l;
                split_hl(g0, h, l);
                outH[(size_t)row*CDIM + gcol] = h; outL[(size_t)row*CDIM + gcol] = l;
                split_hl(g1, h, l);
                outH[(size_t)(row+8)*CDIM + gcol] = h; outL[(size_t)(row+8)*CDIM + gcol] = l;
            }
        }
    } else {
        // EPI 4: residual add then transposed store to [B, C, L] via smem staging
        float* smf = (float*)smem;      // [128 cols][132 row-stride]
        __syncthreads();
        #pragma unroll
        for (int i=0;i<4;i++){
            int row = bm + wm + i*16 + r0;
            int rl  = wm + i*16 + r0;
            #pragma unroll
            for (int j=0;j<4;j++){
                int col = bn + wn + j*8 + cc;
                int clo = wn + j*8 + cc;
                __nv_bfloat162 h0 = *(const __nv_bfloat162*)(e0h + (size_t)row*CDIM + col);
                __nv_bfloat162 l0 = *(const __nv_bfloat162*)(e0l + (size_t)row*CDIM + col);
                __nv_bfloat162 h1 = *(const __nv_bfloat162*)(e0h + (size_t)(row+8)*CDIM + col);
                __nv_bfloat162 l1 = *(const __nv_bfloat162*)(e0l + (size_t)(row+8)*CDIM + col);
                smf[(clo  )*132 + rl    ] = acc[i][j][0] + __bfloat162float(h0.x) + __bfloat162float(l0.x);
                smf[(clo+1)*132 + rl    ] = acc[i][j][1] + __bfloat162float(h0.y) + __bfloat162float(l0.y);
                smf[(clo  )*132 + rl + 8] = acc[i][j][2] + __bfloat162float(h1.x) + __bfloat162float(l1.x);
                smf[(clo+1)*132 + rl + 8] = acc[i][j][3] + __bfloat162float(h1.y) + __bfloat162float(l1.y);
            }
        }
        __syncthreads();
        int b  = bm >> 12;
        int l0 = bm & 4095;
        #pragma unroll
        for (int q = 0; q < 16; q++){
            int cl = w*16 + q;
            float4 v = *(const float4*)(smf + cl*132 + lane*4);
            *(float4*)(Cout + ((size_t)b*CDIM + bn + cl)*LDIM + l0 + lane*4) = v;
        }
    }
}

// ---------------- prep: discretization ----------------
__global__ void prep_lam(const float* __restrict__ Lam, const float* __restrict__ logstep){
    int p = threadIdx.x;
    float step = expf(logstep[p]);
    float lre = Lam[2*p], lim = Lam[2*p+1];
    double a  = exp((double)lre*(double)step);
    double th = (double)lim*(double)step;
    g_lam[2*p]   = (float)(a*cos(th));
    g_lam[2*p+1] = (float)(a*sin(th));
    double aT  = exp((double)TCH*(double)lre*(double)step);
    double thT = (double)TCH*th;
    g_lamT[2*p]   = (float)(aT*cos(thT));
    g_lamT[2*p+1] = (float)(aT*sin(thT));
}

__global__ void prep_wb(const float* __restrict__ Lam, const float* __restrict__ Bmat){
    int p = blockIdx.x, c = threadIdx.x;
    float lre = Lam[2*p], lim = Lam[2*p+1];
    float lbr = g_lam[2*p], lbi = g_lam[2*p+1];
    float den = lre*lre + lim*lim;
    float cr = ((lbr-1.0f)*lre + lbi*lim)/den;
    float ci = (lbi*lre - (lbr-1.0f)*lim)/den;
    float br = Bmat[(p*CDIM + c)*2], bi = Bmat[(p*CDIM + c)*2 + 1];
    float vre = cr*br - ci*bi;
    float vim = cr*bi + ci*br;
    __nv_bfloat16 h,l;
    split_hl(vre,h,l); g_wbh[(size_t)p*CDIM + c]=h;        g_wbl[(size_t)p*CDIM + c]=l;
    split_hl(vim,h,l); g_wbh[(size_t)(PDIM+p)*CDIM + c]=h; g_wbl[(size_t)(PDIM+p)*CDIM + c]=l;
}

__global__ void prep_wc(const float* __restrict__ Lam, const float* __restrict__ logstep,
                        const float* __restrict__ Cmat){
    int hrow = blockIdx.x, p = threadIdx.x;
    float step = expf(logstep[p]);
    float lim = Lam[2*p+1];
    float freq = step*fabsf(lim)*(float)(1.0/(2.0*3.14159265358979323846));
    float m = (freq < 0.25f) ? 2.0f : 0.0f;
    float cre = Cmat[(hrow*PDIM + p)*2], cim = Cmat[(hrow*PDIM + p)*2 + 1];
    __nv_bfloat16 h,l;
    split_hl( m*cre,h,l); g_wch[(size_t)hrow*CDIM + p]=h;        g_wcl[(size_t)hrow*CDIM + p]=l;
    split_hl(-m*cim,h,l); g_wch[(size_t)hrow*CDIM + PDIM + p]=h; g_wcl[(size_t)hrow*CDIM + PDIM + p]=l;
}

// interleave W_enc rows: out row 2t = z1 row t, out row 2t+1 = z2 row (384+t)
__global__ void prep_we(const float* __restrict__ Wenc,
                        __nv_bfloat16* __restrict__ weh, __nv_bfloat16* __restrict__ wel){
    int n = blockIdx.x, c = threadIdx.x;
    int src = (n & 1) ? (CDIM + (n >> 1)) : (n >> 1);
    __nv_bfloat16 h,l;
    split_hl(Wenc[(size_t)src*CDIM + c], h, l);
    weh[(size_t)n*CDIM + c] = h; wel[(size_t)n*CDIM + c] = l;
}

__global__ void cvt_hl(const float* __restrict__ src, __nv_bfloat16* __restrict__ h,
                       __nv_bfloat16* __restrict__ l, int n){
    int i = blockIdx.x*blockDim.x + threadIdx.x;
    if (i < n){ __nv_bfloat16 hh,ll; split_hl(src[i],hh,ll); h[i]=hh; l[i]=ll; }
}

// ---------------- LayerNorm 1 : x[B,C,L] -> hi/lo bf16 [BL,C] ----------------
__global__ __launch_bounds__(256) void ln1_kernel(const float* __restrict__ x,
                                                  const float* __restrict__ gam,
                                                  const float* __restrict__ bet,
                                                  __nv_bfloat16* __restrict__ fxh,
                                                  __nv_bfloat16* __restrict__ fxl){
    __shared__ float tile[CDIM][17];
    int b = blockIdx.y, l0 = blockIdx.x*16;
    int tid = threadIdx.x;
    for (int idx = tid; idx < CDIM*16; idx += 256){
        int c = idx >> 4, j = idx & 15;
        tile[c][j] = x[((size_t)b*CDIM + c)*LDIM + l0 + j];
    }
    __syncthreads();
    int w = tid >> 5, lane = tid & 31;
    for (int j = w*2; j < w*2 + 2; j++){
        float v[12]; float s = 0.0f;
        #pragma unroll
        for (int k = 0; k < 12; k++){ v[k] = tile[lane + 32*k][j]; s += v[k]; }
        #pragma unroll
        for (int o = 16; o; o >>= 1) s += __shfl_xor_sync(0xffffffffu, s, o);
        float mu = s * (1.0f/CDIM);
        float q = 0.0f;
        #pragma unroll
        for (int k = 0; k < 12; k++){ float d = v[k]-mu; q += d*d; }
        #pragma unroll
        for (int o = 16; o; o >>= 1) q += __shfl_xor_sync(0xffffffffu, q, o);
        float inv = rsqrtf(q*(1.0f/CDIM) + 1e-5f);
        size_t row = ((size_t)b*LDIM + l0 + j)*CDIM;
        #pragma unroll
        for (int k = 0; k < 12; k++){
            int c = lane + 32*k;
            float val = (v[k]-mu)*inv*gam[c] + bet[c];
            __nv_bfloat16 h,l; split_hl(val,h,l);
            fxh[row + c] = h; fxl[row + c] = l;
        }
    }
}

// ---------------- LayerNorm 2 : y[BL,C] -> hi/lo ----------------
__global__ __launch_bounds__(256) void ln2_kernel(const float* __restrict__ y,
                                                  const float* __restrict__ gam,
                                                  const float* __restrict__ bet,
                                                  __nv_bfloat16* __restrict__ fyh,
                                                  __nv_bfloat16* __restrict__ fyl){
    int row = blockIdx.x*8 + (threadIdx.x >> 5);
    int lane = threadIdx.x & 31;
    const float4* r4 = (const float4*)(y + (size_t)row*CDIM);
    float4 v[3]; float s = 0.0f;
    #pragma unroll
    for (int k = 0; k < 3; k++){ v[k] = r4[lane + 32*k]; s += v[k].x+v[k].y+v[k].z+v[k].w; }
    #pragma unroll
    for (int o = 16; o; o >>= 1) s += __shfl_xor_sync(0xffffffffu, s, o);
    float mu = s * (1.0f/CDIM);
    float q = 0.0f;
    #pragma unroll
    for (int k = 0; k < 3; k++){
        float dx=v[k].x-mu, dy=v[k].y-mu, dz=v[k].z-mu, dw=v[k].w-mu;
        q += dx*dx+dy*dy+dz*dz+dw*dw;
    }
    #pragma unroll
    for (int o = 16; o; o >>= 1) q += __shfl_xor_sync(0xffffffffu, q, o);
    float inv = rsqrtf(q*(1.0f/CDIM) + 1e-5f);
    #pragma unroll
    for (int k = 0; k < 3; k++){
        int c4 = lane + 32*k;
        float4 gg = ((const float4*)gam)[c4], bb = ((const float4*)bet)[c4];
        float rx = (v[k].x-mu)*inv*gg.x + bb.x;
        float ry = (v[k].y-mu)*inv*gg.y + bb.y;
        float rz = (v[k].z-mu)*inv*gg.z + bb.z;
        float rw = (v[k].w-mu)*inv*gg.w + bb.w;
        size_t base = (size_t)row*CDIM + c4*4;
        __nv_bfloat16 h,l;
        split_hl(rx,h,l); fyh[base+0]=h; fyl[base+0]=l;
        split_hl(ry,h,l); fyh[base+1]=h; fyl[base+1]=l;
        split_hl(rz,h,l); fyh[base+2]=h; fyl[base+2]=l;
        split_hl(rw,h,l); fyh[base+3]=h; fyl[base+3]=l;
    }
}

// ---------------- chunked constant-coefficient complex scan ----------------
// scan_a: compute chunk carry only (read-only over bu)
__global__ void scan_a(const float* __restrict__ bu, float* __restrict__ carry){
    int p = threadIdx.x, ch = blockIdx.x, b = blockIdx.y;
    float lre = g_lam[2*p], lim = g_lam[2*p+1];
    float sre = 0.0f, sim = 0.0f;
    size_t base = ((size_t)b*LDIM + (size_t)ch*TCH)*CDIM;
    for (int i = 0; i < TCH; i++){
        size_t idx = base + (size_t)i*CDIM;
        float br = bu[idx+p], bi = bu[idx+PDIM+p];
        float nr = fmaf(lre, sre, fmaf(-lim, sim, br));
        float ni = fmaf(lre, sim, fmaf( lim, sre, bi));
        sre = nr; sim = ni;
    }
    size_t cidx = ((size_t)b*NCH + ch)*CDIM;
    carry[cidx+p] = sre; carry[cidx+PDIM+p] = sim;
}

__global__ void scan_b(float* __restrict__ carry){
    int p = threadIdx.x, b = blockIdx.x;
    float tr = g_lamT[2*p], ti = g_lamT[2*p+1];
    float pr = 0.0f, pi = 0.0f;
    for (int k = 0; k < NCH; k++){
        size_t ci = ((size_t)b*NCH + k)*CDIM;
        float cr = carry[ci+p], cm = carry[ci+PDIM+p];
        carry[ci+p] = pr; carry[ci+PDIM+p] = pi;      // exclusive prefix
        float nr = fmaf(tr, pr, fmaf(-ti, pi, cr));
        float ni = fmaf(tr, pi, fmaf( ti, pr, cm));
        pr = nr; pi = ni;
    }
}

// scan_c: full local recurrence seeded by carry prefix; emit xs hi/lo
__global__ void scan_c(const float* __restrict__ bu, const float* __restrict__ carry,
                       __nv_bfloat16* __restrict__ bh, __nv_bfloat16* __restrict__ bl){
    int p = threadIdx.x, ch = blockIdx.x, b = blockIdx.y;
    size_t cidx = ((size_t)b*NCH + ch)*CDIM;
    float sre = carry[cidx+p], sim = carry[cidx+PDIM+p];   // ch==0 prefix is 0
    float lre = g_lam[2*p], lim = g_lam[2*p+1];
    size_t base = ((size_t)b*LDIM + (size_t)ch*TCH)*CDIM;
    for (int i = 0; i < TCH; i++){
        size_t idx = base + (size_t)i*CDIM;
        float br = bu[idx+p], bi = bu[idx+PDIM+p];
        float nr = fmaf(lre, sre, fmaf(-lim, sim, br));
        float ni = fmaf(lre, sim, fmaf( lim, sre, bi));
        sre = nr; sim = ni;
        __nv_bfloat16 h,l;
        split_hl(nr,h,l); bh[idx+p]=h;      bl[idx+p]=l;
        split_hl(ni,h,l); bh[idx+PDIM+p]=h; bl[idx+PDIM+p]=l;
    }
}

// ---------------- launch ----------------
extern "C" void kernel_launch(void* const* d_in, const int* in_sizes, int n_in,
                              void* d_out, int out_size){
    const float* x       = (const float*)d_in[0];
    const float* ln1g    = (const float*)d_in[1];
    const float* ln1b    = (const float*)d_in[2];
    const float* Lam     = (const float*)d_in[3];
    const float* Bmat    = (const float*)d_in[4];
    const float* Cmat    = (const float*)d_in[5];
    const float* Dv      = (const float*)d_in[6];
    const float* logstep = (const float*)d_in[7];
    const float* ln2g    = (const float*)d_in[8];
    const float* ln2b    = (const float*)d_in[9];
    const float* Wenc    = (const float*)d_in[10];
    const float* Wdec    = (const float*)d_in[11];
    float* out = (float*)d_out;

    float *bu,*y,*carry;
    cudaGetSymbolAddress((void**)&bu,    g_bu);
    cudaGetSymbolAddress((void**)&y,     g_y);
    cudaGetSymbolAddress((void**)&carry, g_carry);

    __nv_bfloat16 *fxh,*fxl,*buh,*bul,*fyh,*fyl,*ggh,*ggl;
    __nv_bfloat16 *wbh,*wbl,*wch,*wcl,*weh,*wel,*wdh,*wdl;
    cudaGetSymbolAddress((void**)&fxh, g_fxh); cudaGetSymbolAddress((void**)&fxl, g_fxl);
    cudaGetSymbolAddress((void**)&buh, g_buh); cudaGetSymbolAddress((void**)&bul, g_bul);
    cudaGetSymbolAddress((void**)&fyh, g_fyh); cudaGetSymbolAddress((void**)&fyl, g_fyl);
    cudaGetSymbolAddress((void**)&ggh, g_ggh); cudaGetSymbolAddress((void**)&ggl, g_ggl);
    cudaGetSymbolAddress((void**)&wbh, g_wbh); cudaGetSymbolAddress((void**)&wbl, g_wbl);
    cudaGetSymbolAddress((void**)&wch, g_wch); cudaGetSymbolAddress((void**)&wcl, g_wcl);
    cudaGetSymbolAddress((void**)&weh, g_weh); cudaGetSymbolAddress((void**)&wel, g_wel);
    cudaGetSymbolAddress((void**)&wdh, g_wdh); cudaGetSymbolAddress((void**)&wdl, g_wdl);

    const int SMEM_GEMM = 2*40960;   // 80 KB (also covers 128x132 fp32 transpose staging)
    cudaFuncSetAttribute(mma_gemm<0>, cudaFuncAttributeMaxDynamicSharedMemorySize, SMEM_GEMM);
    cudaFuncSetAttribute(mma_gemm<1>, cudaFuncAttributeMaxDynamicSharedMemorySize, SMEM_GEMM);
    cudaFuncSetAttribute(mma_gemm<3>, cudaFuncAttributeMaxDynamicSharedMemorySize, SMEM_GEMM);
    cudaFuncSetAttribute(mma_gemm<4>, cudaFuncAttributeMaxDynamicSharedMemorySize, SMEM_GEMM);

    prep_lam<<<1, PDIM>>>(Lam, logstep);
    prep_wb<<<PDIM, CDIM>>>(Lam, Bmat);
    prep_wc<<<CDIM, PDIM>>>(Lam, logstep, Cmat);
    prep_we<<<2*CDIM, CDIM>>>(Wenc, weh, wel);
    cvt_hl<<<(CDIM*CDIM + 255)/256, 256>>>(Wdec, wdh, wdl, CDIM*CDIM);

    ln1_kernel<<<dim3(LDIM/16, BSZ), 256>>>(x, ln1g, ln1b, fxh, fxl);

    // Bu = fx @ Bbar_packed^T   -> [BL, 2P] fp32
    mma_gemm<0><<<dim3(3, 512), 256, SMEM_GEMM>>>(fxh, fxl, wbh, wbl, bu, CDIM,
                                                  nullptr, nullptr, nullptr, nullptr, nullptr);

    scan_a<<<dim3(NCH, BSZ), PDIM>>>(bu, carry);
    scan_b<<<BSZ, PDIM>>>(carry);
    scan_c<<<dim3(NCH, BSZ), PDIM>>>(bu, carry, buh, bul);

    // y = gelu(xs @ Ceff^T + D*fx) + fx
    mma_gemm<1><<<dim3(3, 512), 256, SMEM_GEMM>>>(buh, bul, wch, wcl, y, CDIM,
                                                  nullptr, nullptr, fxh, fxl, Dv);

    ln2_kernel<<<BLTOK/8, 256>>>(y, ln2g, ln2b, fyh, fyl);

    // gg = GEGLU(fy @ Wenc_interleaved^T)  -> bf16 hi/lo [BL, 384] directly
    mma_gemm<3><<<dim3(6, 512), 256, SMEM_GEMM>>>(fyh, fyl, weh, wel, nullptr, CDIM,
                                                  ggh, ggl, nullptr, nullptr, nullptr);

    // out = transpose(gg @ Wdec^T + fy)  (written straight to [B,C,L])
    mma_gemm<4><<<dim3(3, 512), 256, SMEM_GEMM>>>(ggh, ggl, wdh, wdl, out, CDIM,
                                                  nullptr, nullptr, fyh, fyl, nullptr);
}

// round 6
// speedup vs baseline: 3.1597x; 1.3743x over previous
#include <cuda_runtime.h>
#include <cuda_fp16.h>
#include <math.h>
#include <stdint.h>

#define BSZ  16
#define CDIM 384
#define LDIM 4096
#define PDIM 192
#define BLTOK (BSZ*LDIM)      // 65536
#define NCH  64
#define TCH  64
#define KDIM 384

// ---------------- static scratch (no allocations allowed) ----------------
__device__ float g_bu[(size_t)BLTOK*CDIM];   // Bu fp32 (pre-scan)
__device__ float g_y [(size_t)BLTOK*CDIM];
__device__ float g_lam [2*PDIM];
__device__ float g_lamT[2*PDIM];
__device__ float g_carry[(size_t)BSZ*NCH*CDIM];

// fp16 operands: activations hi/lo, weights single fp16
__device__ __half g_fxh[(size_t)BLTOK*CDIM], g_fxl[(size_t)BLTOK*CDIM];
__device__ __half g_buh[(size_t)BLTOK*CDIM], g_bul[(size_t)BLTOK*CDIM];
__device__ __half g_fyh[(size_t)BLTOK*CDIM], g_fyl[(size_t)BLTOK*CDIM];
__device__ __half g_ggh[(size_t)BLTOK*CDIM], g_ggl[(size_t)BLTOK*CDIM];
__device__ __half g_wb[CDIM*CDIM];
__device__ __half g_wc[CDIM*CDIM];
__device__ __half g_we[2*CDIM*CDIM];   // interleaved z1/z2 rows
__device__ __half g_wd[CDIM*CDIM];

__device__ __forceinline__ float gelu_f(float v){
    return 0.5f*v*(1.0f + erff(v*0.70710678118654752f));
}
__device__ __forceinline__ void split_hl(float v, __half& h, __half& l){
    h = __float2half_rn(v);
    l = __float2half_rn(v - __half2float(h));
}
__device__ __forceinline__ uint32_t smem_u32(const void* p){
    uint32_t a;
    asm("{ .reg .u64 t; cvta.to.shared.u64 t, %1; cvt.u32.u64 %0, t; }" : "=r"(a) : "l"(p));
    return a;
}

// ---------------- MMA / ldmatrix / cp.async primitives (sm_80+ neutral PTX) ----------------
#define CP16(sa, ga)  asm volatile("cp.async.cg.shared.global [%0], [%1], 16;" :: "r"(sa), "l"(ga))
#define CPCOMMIT()    asm volatile("cp.async.commit_group;")
#define CPWAIT(n)     asm volatile("cp.async.wait_group %0;" :: "n"(n))

#define LDSM4(r, addr) asm volatile( \
    "ldmatrix.sync.aligned.m8n8.x4.shared.b16 {%0,%1,%2,%3}, [%4];" \
    : "=r"((r)[0]),"=r"((r)[1]),"=r"((r)[2]),"=r"((r)[3]) : "r"(addr))

#define MMA(d, a, b0v, b1v) asm volatile( \
    "mma.sync.aligned.m16n8k16.row.col.f32.f16.f16.f32 " \
    "{%0,%1,%2,%3},{%4,%5,%6,%7},{%8,%9},{%0,%1,%2,%3};" \
    : "+f"((d)[0]),"+f"((d)[1]),"+f"((d)[2]),"+f"((d)[3]) \
    : "r"((a)[0]),"r"((a)[1]),"r"((a)[2]),"r"((a)[3]),"r"(b0v),"r"(b1v))

// ============ fp16 (A hi/lo split) NT GEMM: C[M,*] = A[M,384] @ B[*,384]^T ============
// tile 128x128, BK=32, 3-stage cp.async (1 sync/chunk), warp grid 2x4 (64x32 warp tiles)
// stage layout: Ahi @0, Alo @10240, B @20480 ; stage stride 30720 ; rows padded to 80B
// EPI 0: Cout fp32 plain
// EPI 1: f=e0h+e0l; v=acc+e1[n]*f; Cout=gelu(v)+f   (fp32)
// EPI 3: GEGLU pairs -> smem staged -> outH/outL fp16 [BL, 384]
// EPI 4: f=e0h+e0l; o=acc+f; write Cout transposed [B,C,L] via smem staging
template<int EPI>
__global__ __launch_bounds__(256,2) void mma_gemm(
    const __half* __restrict__ Ah, const __half* __restrict__ Al,
    const __half* __restrict__ Bm,
    float* __restrict__ Cout, int Nout,
    __half* __restrict__ outH, __half* __restrict__ outL,
    const __half* __restrict__ e0h, const __half* __restrict__ e0l,
    const float* __restrict__ e1)
{
    extern __shared__ char smem[];
    uint32_t sb = smem_u32(smem);
    const int tid = threadIdx.x;
    const int bm = blockIdx.y*128, bn = blockIdx.x*128;

    // ---- load indexing: rows lr, lr+64 ; seg = 16B segment within 64B row ----
    const int lr  = tid >> 2;
    const int seg = tid & 3;
    const __half* pa0h = Ah + (size_t)(bm+lr)*KDIM + seg*8;
    const __half* pa0l = Al + (size_t)(bm+lr)*KDIM + seg*8;
    const __half* pb0  = Bm + (size_t)(bn+lr)*KDIM + seg*8;
    const uint32_t s0 = lr*80 + seg*16;

    // ---- compute indexing ----
    const int lane = tid & 31, w = tid >> 5;
    const int wm = (w >> 2)*64, wn = (w & 3)*32;
    const uint32_t aoff = (uint32_t)(wm + (lane & 15))*80 + (lane >> 4)*16;
    const int bg = lane >> 3, blg = lane & 7;
    const uint32_t boff = (uint32_t)(wn + (bg >> 1)*8 + blg)*80 + (bg & 1)*16;

    float acc[4][4][4];
    #pragma unroll
    for (int i=0;i<4;i++)
        #pragma unroll
        for (int j=0;j<4;j++)
            #pragma unroll
            for (int q=0;q<4;q++) acc[i][j][q]=0.f;

    auto issue = [&](int st, int kc){
        uint32_t sbase = sb + st*30720;
        #pragma unroll
        for (int h = 0; h < 2; h++){
            size_t rofs = (size_t)kc + (size_t)h*64*KDIM;
            uint32_t sa = sbase + s0 + h*64*80;
            CP16(sa,         pa0h + rofs);
            CP16(sa + 10240, pa0l + rofs);
            CP16(sa + 20480, pb0  + rofs);
        }
        CPCOMMIT();
    };

    issue(0, 0);
    issue(1, 32);
    int stg = 0;                        // stage of chunk c
    #pragma unroll 1
    for (int c = 0; c < 12; c++){
        if (c < 11) { CPWAIT(1); } else { CPWAIT(0); }
        __syncthreads();
        if (c + 2 < 12){
            int st2 = stg + 2; if (st2 >= 3) st2 -= 3;
            issue(st2, (c+2)*32);
        }
        uint32_t base = sb + stg*30720;
        #pragma unroll
        for (int ks = 0; ks < 2; ks++){
            uint32_t kb = ks*32;
            uint32_t a[4][4], bf[4][2], t[4];
            #pragma unroll
            for (int i=0;i<4;i++) LDSM4(a[i], base + aoff + i*16*80 + kb);          // A hi
            #pragma unroll
            for (int jp=0;jp<2;jp++){
                LDSM4(t, base + 20480 + boff + jp*16*80 + kb);                      // B
                bf[2*jp][0]=t[0]; bf[2*jp][1]=t[1]; bf[2*jp+1][0]=t[2]; bf[2*jp+1][1]=t[3];
            }
            #pragma unroll
            for (int i=0;i<4;i++)
                #pragma unroll
                for (int j=0;j<4;j++) MMA(acc[i][j], a[i], bf[j][0], bf[j][1]);     // Ahi*B
            #pragma unroll
            for (int i=0;i<4;i++) LDSM4(a[i], base + 10240 + aoff + i*16*80 + kb);  // A lo
            #pragma unroll
            for (int i=0;i<4;i++)
                #pragma unroll
                for (int j=0;j<4;j++) MMA(acc[i][j], a[i], bf[j][0], bf[j][1]);     // Alo*B
        }
        if (++stg == 3) stg = 0;
    }

    // ---- epilogue ----
    const int r0 = lane >> 2, cc = (lane & 3)*2;
    if (EPI == 0 || EPI == 1){
        #pragma unroll
        for (int i=0;i<4;i++){
            int row = bm + wm + i*16 + r0;
            #pragma unroll
            for (int j=0;j<4;j++){
                int col = bn + wn + j*8 + cc;
                float v0 = acc[i][j][0], v1 = acc[i][j][1];
                float v2 = acc[i][j][2], v3 = acc[i][j][3];
                if (EPI == 1){
                    float2 d2 = *(const float2*)(e1 + col);
                    __half2 h0 = *(const __half2*)(e0h + (size_t)row*CDIM + col);
                    __half2 l0 = *(const __half2*)(e0l + (size_t)row*CDIM + col);
                    __half2 h1 = *(const __half2*)(e0h + (size_t)(row+8)*CDIM + col);
                    __half2 l1 = *(const __half2*)(e0l + (size_t)(row+8)*CDIM + col);
                    float f0x = __half2float(h0.x) + __half2float(l0.x);
                    float f0y = __half2float(h0.y) + __half2float(l0.y);
                    float f1x = __half2float(h1.x) + __half2float(l1.x);
                    float f1y = __half2float(h1.y) + __half2float(l1.y);
                    v0 = gelu_f(v0 + d2.x*f0x) + f0x;
                    v1 = gelu_f(v1 + d2.y*f0y) + f0y;
                    v2 = gelu_f(v2 + d2.x*f1x) + f1x;
                    v3 = gelu_f(v3 + d2.y*f1y) + f1y;
                }
                *(float2*)(Cout + (size_t)row*Nout + col)     = make_float2(v0, v1);
                *(float2*)(Cout + (size_t)(row+8)*Nout + col) = make_float2(v2, v3);
            }
        }
    } else if (EPI == 3){
        // GEGLU: even col = z1, odd col = z2 (interleaved W_enc); stage hi/lo packed in smem
        uint32_t* st = (uint32_t*)smem;    // [128 rows][66] packed (hi,lo)
        __syncthreads();
        #pragma unroll
        for (int i=0;i<4;i++){
            int rl = wm + i*16 + r0;
            #pragma unroll
            for (int j=0;j<4;j++){
                int gcl = (wn >> 1) + j*4 + (lane & 3);
                float g0 = acc[i][j][0] * gelu_f(acc[i][j][1]);
                float g1 = acc[i][j][2] * gelu_f(acc[i][j][3]);
                __half h, l;
                split_hl(g0, h, l);
                st[rl*66 + gcl] = (uint32_t)__half_as_ushort(h) | ((uint32_t)__half_as_ushort(l) << 16);
                split_hl(g1, h, l);
                st[(rl+8)*66 + gcl] = (uint32_t)__half_as_ushort(h) | ((uint32_t)__half_as_ushort(l) << 16);
            }
        }
        __syncthreads();
        int gcol0 = bn >> 1;
        #pragma unroll
        for (int q = 0; q < 16; q++){
            int rl = w*16 + q;
            size_t gb = (size_t)(bm + rl)*CDIM + gcol0 + 2*lane;
            uint32_t v0 = st[rl*66 + 2*lane];
            uint32_t v1 = st[rl*66 + 2*lane + 1];
            uint32_t hh = (v0 & 0xffffu) | (v1 << 16);
            uint32_t ll = (v0 >> 16) | (v1 & 0xffff0000u);
            *(uint32_t*)(outH + gb) = hh;
            *(uint32_t*)(outL + gb) = ll;
        }
    } else {
        // EPI 4: residual add then transposed store to [B, C, L] via smem staging
        float* smf = (float*)smem;      // [128 cols][132 row-stride]
        __syncthreads();
        #pragma unroll
        for (int i=0;i<4;i++){
            int row = bm + wm + i*16 + r0;
            int rl  = wm + i*16 + r0;
            #pragma unroll
            for (int j=0;j<4;j++){
                int col = bn + wn + j*8 + cc;
                int clo = wn + j*8 + cc;
                __half2 h0 = *(const __half2*)(e0h + (size_t)row*CDIM + col);
                __half2 l0 = *(const __half2*)(e0l + (size_t)row*CDIM + col);
                __half2 h1 = *(const __half2*)(e0h + (size_t)(row+8)*CDIM + col);
                __half2 l1 = *(const __half2*)(e0l + (size_t)(row+8)*CDIM + col);
                smf[(clo  )*132 + rl    ] = acc[i][j][0] + __half2float(h0.x) + __half2float(l0.x);
                smf[(clo+1)*132 + rl    ] = acc[i][j][1] + __half2float(h0.y) + __half2float(l0.y);
                smf[(clo  )*132 + rl + 8] = acc[i][j][2] + __half2float(h1.x) + __half2float(l1.x);
                smf[(clo+1)*132 + rl + 8] = acc[i][j][3] + __half2float(h1.y) + __half2float(l1.y);
            }
        }
        __syncthreads();
        int b  = bm >> 12;
        int l0 = bm & 4095;
        #pragma unroll
        for (int q = 0; q < 16; q++){
            int cl = w*16 + q;
            float4 v = *(const float4*)(smf + cl*132 + lane*4);
            *(float4*)(Cout + ((size_t)b*CDIM + bn + cl)*LDIM + l0 + lane*4) = v;
        }
    }
}

// ---------------- prep: discretization ----------------
__global__ void prep_lam(const float* __restrict__ Lam, const float* __restrict__ logstep){
    int p = threadIdx.x;
    float step = expf(logstep[p]);
    float lre = Lam[2*p], lim = Lam[2*p+1];
    double a  = exp((double)lre*(double)step);
    double th = (double)lim*(double)step;
    g_lam[2*p]   = (float)(a*cos(th));
    g_lam[2*p+1] = (float)(a*sin(th));
    double aT  = exp((double)TCH*(double)lre*(double)step);
    double thT = (double)TCH*th;
    g_lamT[2*p]   = (float)(aT*cos(thT));
    g_lamT[2*p+1] = (float)(aT*sin(thT));
}

__global__ void prep_wb(const float* __restrict__ Lam, const float* __restrict__ Bmat){
    int p = blockIdx.x, c = threadIdx.x;
    float lre = Lam[2*p], lim = Lam[2*p+1];
    float lbr = g_lam[2*p], lbi = g_lam[2*p+1];
    float den = lre*lre + lim*lim;
    float cr = ((lbr-1.0f)*lre + lbi*lim)/den;
    float ci = (lbi*lre - (lbr-1.0f)*lim)/den;
    float br = Bmat[(p*CDIM + c)*2], bi = Bmat[(p*CDIM + c)*2 + 1];
    g_wb[(size_t)p*CDIM + c]        = __float2half_rn(cr*br - ci*bi);
    g_wb[(size_t)(PDIM+p)*CDIM + c] = __float2half_rn(cr*bi + ci*br);
}

__global__ void prep_wc(const float* __restrict__ Lam, const float* __restrict__ logstep,
                        const float* __restrict__ Cmat){
    int hrow = blockIdx.x, p = threadIdx.x;
    float step = expf(logstep[p]);
    float lim = Lam[2*p+1];
    float freq = step*fabsf(lim)*(float)(1.0/(2.0*3.14159265358979323846));
    float m = (freq < 0.25f) ? 2.0f : 0.0f;
    float cre = Cmat[(hrow*PDIM + p)*2], cim = Cmat[(hrow*PDIM + p)*2 + 1];
    g_wc[(size_t)hrow*CDIM + p]        = __float2half_rn( m*cre);
    g_wc[(size_t)hrow*CDIM + PDIM + p] = __float2half_rn(-m*cim);
}

// interleave W_enc rows: out row 2t = z1 row t, out row 2t+1 = z2 row (384+t)
__global__ void prep_we(const float* __restrict__ Wenc, __half* __restrict__ we){
    int n = blockIdx.x, c = threadIdx.x;
    int src = (n & 1) ? (CDIM + (n >> 1)) : (n >> 1);
    we[(size_t)n*CDIM + c] = __float2half_rn(Wenc[(size_t)src*CDIM + c]);
}

__global__ void cvt_h(const float* __restrict__ src, __half* __restrict__ h, int n){
    int i = blockIdx.x*blockDim.x + threadIdx.x;
    if (i < n) h[i] = __float2half_rn(src[i]);
}

// ---------------- LayerNorm 1 : x[B,C,L] -> hi/lo fp16 [BL,C] ----------------
__global__ __launch_bounds__(256) void ln1_kernel(const float* __restrict__ x,
                                                  const float* __restrict__ gam,
                                                  const float* __restrict__ bet,
                                                  __half* __restrict__ fxh,
                                                  __half* __restrict__ fxl){
    __shared__ float tile[CDIM][17];
    int b = blockIdx.y, l0 = blockIdx.x*16;
    int tid = threadIdx.x;
    for (int idx = tid; idx < CDIM*16; idx += 256){
        int c = idx >> 4, j = idx & 15;
        tile[c][j] = x[((size_t)b*CDIM + c)*LDIM + l0 + j];
    }
    __syncthreads();
    int w = tid >> 5, lane = tid & 31;
    for (int j = w*2; j < w*2 + 2; j++){
        float v[12]; float s = 0.0f;
        #pragma unroll
        for (int k = 0; k < 12; k++){ v[k] = tile[lane + 32*k][j]; s += v[k]; }
        #pragma unroll
        for (int o = 16; o; o >>= 1) s += __shfl_xor_sync(0xffffffffu, s, o);
        float mu = s * (1.0f/CDIM);
        float q = 0.0f;
        #pragma unroll
        for (int k = 0; k < 12; k++){ float d = v[k]-mu; q += d*d; }
        #pragma unroll
        for (int o = 16; o; o >>= 1) q += __shfl_xor_sync(0xffffffffu, q, o);
        float inv = rsqrtf(q*(1.0f/CDIM) + 1e-5f);
        size_t row = ((size_t)b*LDIM + l0 + j)*CDIM;
        #pragma unroll
        for (int k = 0; k < 12; k++){
            int c = lane + 32*k;
            float val = (v[k]-mu)*inv*gam[c] + bet[c];
            __half h,l; split_hl(val,h,l);
            fxh[row + c] = h; fxl[row + c] = l;
        }
    }
}

// ---------------- LayerNorm 2 : y[BL,C] -> hi/lo ----------------
__global__ __launch_bounds__(256) void ln2_kernel(const float* __restrict__ y,
                                                  const float* __restrict__ gam,
                                                  const float* __restrict__ bet,
                                                  __half* __restrict__ fyh,
                                                  __half* __restrict__ fyl){
    int row = blockIdx.x*8 + (threadIdx.x >> 5);
    int lane = threadIdx.x & 31;
    const float4* r4 = (const float4*)(y + (size_t)row*CDIM);
    float4 v[3]; float s = 0.0f;
    #pragma unroll
    for (int k = 0; k < 3; k++){ v[k] = r4[lane + 32*k]; s += v[k].x+v[k].y+v[k].z+v[k].w; }
    #pragma unroll
    for (int o = 16; o; o >>= 1) s += __shfl_xor_sync(0xffffffffu, s, o);
    float mu = s * (1.0f/CDIM);
    float q = 0.0f;
    #pragma unroll
    for (int k = 0; k < 3; k++){
        float dx=v[k].x-mu, dy=v[k].y-mu, dz=v[k].z-mu, dw=v[k].w-mu;
        q += dx*dx+dy*dy+dz*dz+dw*dw;
    }
    #pragma unroll
    for (int o = 16; o; o >>= 1) q += __shfl_xor_sync(0xffffffffu, q, o);
    float inv = rsqrtf(q*(1.0f/CDIM) + 1e-5f);
    #pragma unroll
    for (int k = 0; k < 3; k++){
        int c4 = lane + 32*k;
        float4 gg = ((const float4*)gam)[c4], bb = ((const float4*)bet)[c4];
        float rx = (v[k].x-mu)*inv*gg.x + bb.x;
        float ry = (v[k].y-mu)*inv*gg.y + bb.y;
        float rz = (v[k].z-mu)*inv*gg.z + bb.z;
        float rw = (v[k].w-mu)*inv*gg.w + bb.w;
        size_t base = (size_t)row*CDIM + c4*4;
        __half h,l;
        split_hl(rx,h,l); fyh[base+0]=h; fyl[base+0]=l;
        split_hl(ry,h,l); fyh[base+1]=h; fyl[base+1]=l;
        split_hl(rz,h,l); fyh[base+2]=h; fyl[base+2]=l;
        split_hl(rw,h,l); fyh[base+3]=h; fyl[base+3]=l;
    }
}

// ---------------- chunked constant-coefficient complex scan ----------------
__global__ void scan_a(const float* __restrict__ bu, float* __restrict__ carry){
    int p = threadIdx.x, ch = blockIdx.x, b = blockIdx.y;
    float lre = g_lam[2*p], lim = g_lam[2*p+1];
    float sre = 0.0f, sim = 0.0f;
    size_t base = ((size_t)b*LDIM + (size_t)ch*TCH)*CDIM;
    for (int i = 0; i < TCH; i++){
        size_t idx = base + (size_t)i*CDIM;
        float br = bu[idx+p], bi = bu[idx+PDIM+p];
        float nr = fmaf(lre, sre, fmaf(-lim, sim, br));
        float ni = fmaf(lre, sim, fmaf( lim, sre, bi));
        sre = nr; sim = ni;
    }
    size_t cidx = ((size_t)b*NCH + ch)*CDIM;
    carry[cidx+p] = sre; carry[cidx+PDIM+p] = sim;
}

__global__ void scan_b(float* __restrict__ carry){
    int p = threadIdx.x, b = blockIdx.x;
    float tr = g_lamT[2*p], ti = g_lamT[2*p+1];
    float pr = 0.0f, pi = 0.0f;
    for (int k = 0; k < NCH; k++){
        size_t ci = ((size_t)b*NCH + k)*CDIM;
        float cr = carry[ci+p], cm = carry[ci+PDIM+p];
        carry[ci+p] = pr; carry[ci+PDIM+p] = pi;      // exclusive prefix
        float nr = fmaf(tr, pr, fmaf(-ti, pi, cr));
        float ni = fmaf(tr, pi, fmaf( ti, pr, cm));
        pr = nr; pi = ni;
    }
}

// scan_c: full local recurrence seeded by carry prefix; emit xs hi/lo fp16
__global__ void scan_c(const float* __restrict__ bu, const float* __restrict__ carry,
                       __half* __restrict__ bh, __half* __restrict__ bl){
    int p = threadIdx.x, ch = blockIdx.x, b = blockIdx.y;
    size_t cidx = ((size_t)b*NCH + ch)*CDIM;
    float sre = carry[cidx+p], sim = carry[cidx+PDIM+p];   // ch==0 prefix is 0
    float lre = g_lam[2*p], lim = g_lam[2*p+1];
    size_t base = ((size_t)b*LDIM + (size_t)ch*TCH)*CDIM;
    for (int i = 0; i < TCH; i++){
        size_t idx = base + (size_t)i*CDIM;
        float br = bu[idx+p], bi = bu[idx+PDIM+p];
        float nr = fmaf(lre, sre, fmaf(-lim, sim, br));
        float ni = fmaf(lre, sim, fmaf( lim, sre, bi));
        sre = nr; sim = ni;
        __half h,l;
        split_hl(nr,h,l); bh[idx+p]=h;      bl[idx+p]=l;
        split_hl(ni,h,l); bh[idx+PDIM+p]=h; bl[idx+PDIM+p]=l;
    }
}

// ---------------- launch ----------------
extern "C" void kernel_launch(void* const* d_in, const int* in_sizes, int n_in,
                              void* d_out, int out_size){
    const float* x       = (const float*)d_in[0];
    const float* ln1g    = (const float*)d_in[1];
    const float* ln1b    = (const float*)d_in[2];
    const float* Lam     = (const float*)d_in[3];
    const float* Bmat    = (const float*)d_in[4];
    const float* Cmat    = (const float*)d_in[5];
    const float* Dv      = (const float*)d_in[6];
    const float* logstep = (const float*)d_in[7];
    const float* ln2g    = (const float*)d_in[8];
    const float* ln2b    = (const float*)d_in[9];
    const float* Wenc    = (const float*)d_in[10];
    const float* Wdec    = (const float*)d_in[11];
    float* out = (float*)d_out;

    float *bu,*y,*carry;
    cudaGetSymbolAddress((void**)&bu,    g_bu);
    cudaGetSymbolAddress((void**)&y,     g_y);
    cudaGetSymbolAddress((void**)&carry, g_carry);

    __half *fxh,*fxl,*buh,*bul,*fyh,*fyl,*ggh,*ggl,*wb,*wc,*we,*wd;
    cudaGetSymbolAddress((void**)&fxh, g_fxh); cudaGetSymbolAddress((void**)&fxl, g_fxl);
    cudaGetSymbolAddress((void**)&buh, g_buh); cudaGetSymbolAddress((void**)&bul, g_bul);
    cudaGetSymbolAddress((void**)&fyh, g_fyh); cudaGetSymbolAddress((void**)&fyl, g_fyl);
    cudaGetSymbolAddress((void**)&ggh, g_ggh); cudaGetSymbolAddress((void**)&ggl, g_ggl);
    cudaGetSymbolAddress((void**)&wb,  g_wb);  cudaGetSymbolAddress((void**)&wc,  g_wc);
    cudaGetSymbolAddress((void**)&we,  g_we);  cudaGetSymbolAddress((void**)&wd,  g_wd);

    const int SMEM_GEMM = 3*30720;   // 92160 B (3-stage; also covers epilogue staging)
    cudaFuncSetAttribute(mma_gemm<0>, cudaFuncAttributeMaxDynamicSharedMemorySize, SMEM_GEMM);
    cudaFuncSetAttribute(mma_gemm<1>, cudaFuncAttributeMaxDynamicSharedMemorySize, SMEM_GEMM);
    cudaFuncSetAttribute(mma_gemm<3>, cudaFuncAttributeMaxDynamicSharedMemorySize, SMEM_GEMM);
    cudaFuncSetAttribute(mma_gemm<4>, cudaFuncAttributeMaxDynamicSharedMemorySize, SMEM_GEMM);

    prep_lam<<<1, PDIM>>>(Lam, logstep);
    prep_wb<<<PDIM, CDIM>>>(Lam, Bmat);
    prep_wc<<<CDIM, PDIM>>>(Lam, logstep, Cmat);
    prep_we<<<2*CDIM, CDIM>>>(Wenc, we);
    cvt_h<<<(CDIM*CDIM + 255)/256, 256>>>(Wdec, wd, CDIM*CDIM);

    ln1_kernel<<<dim3(LDIM/16, BSZ), 256>>>(x, ln1g, ln1b, fxh, fxl);

    // Bu = fx @ Bbar_packed^T   -> [BL, 2P] fp32
    mma_gemm<0><<<dim3(3, 512), 256, SMEM_GEMM>>>(fxh, fxl, wb, bu, CDIM,
                                                  nullptr, nullptr, nullptr, nullptr, nullptr);

    scan_a<<<dim3(NCH, BSZ), PDIM>>>(bu, carry);
    scan_b<<<BSZ, PDIM>>>(carry);
    scan_c<<<dim3(NCH, BSZ), PDIM>>>(bu, carry, buh, bul);

    // y = gelu(xs @ Ceff^T + D*fx) + fx
    mma_gemm<1><<<dim3(3, 512), 256, SMEM_GEMM>>>(buh, bul, wc, y, CDIM,
                                                  nullptr, nullptr, fxh, fxl, Dv);

    ln2_kernel<<<BLTOK/8, 256>>>(y, ln2g, ln2b, fyh, fyl);

    // gg = GEGLU(fy @ Wenc_interleaved^T)  -> fp16 hi/lo [BL, 384] directly
    mma_gemm<3><<<dim3(6, 512), 256, SMEM_GEMM>>>(fyh, fyl, we, nullptr, CDIM,
                                                  ggh, ggl, nullptr, nullptr, nullptr);

    // out = transpose(gg @ Wdec^T + fy)  (written straight to [B,C,L])
    mma_gemm<4><<<dim3(3, 512), 256, SMEM_GEMM>>>(ggh, ggl, wd, out, CDIM,
                                                  nullptr, nullptr, fyh, fyl, nullptr);
}

// round 7
// speedup vs baseline: 4.2778x; 1.3539x over previous
#include <cuda_runtime.h>
#include <cuda_fp16.h>
#include <math.h>
#include <stdint.h>

#define BSZ  16
#define CDIM 384
#define LDIM 4096
#define PDIM 192
#define BLTOK (BSZ*LDIM)      // 65536
#define NCH  64
#define TCH  64
#define KDIM 384

// ---------------- static scratch (no allocations allowed) ----------------
__device__ float g_bu[(size_t)BLTOK*CDIM];   // Bu fp32 (pre-scan)
__device__ float g_y [(size_t)BLTOK*CDIM];
__device__ float g_lam [2*PDIM];
__device__ float g_lamT[2*PDIM];
__device__ float g_carry[(size_t)BSZ*NCH*CDIM];

// fp16 operands; lo-arrays only where an epilogue residual needs full accuracy
__device__ __half g_fxh[(size_t)BLTOK*CDIM], g_fxl[(size_t)BLTOK*CDIM];
__device__ __half g_buh[(size_t)BLTOK*CDIM];
__device__ __half g_fyh[(size_t)BLTOK*CDIM], g_fyl[(size_t)BLTOK*CDIM];
__device__ __half g_ggh[(size_t)BLTOK*CDIM];
__device__ __half g_wb[CDIM*CDIM];
__device__ __half g_wc[CDIM*CDIM];
__device__ __half g_we[2*CDIM*CDIM];   // interleaved z1/z2 rows
__device__ __half g_wd[CDIM*CDIM];

__device__ __forceinline__ float gelu_f(float v){
    return 0.5f*v*(1.0f + erff(v*0.70710678118654752f));
}
__device__ __forceinline__ void split_hl(float v, __half& h, __half& l){
    h = __float2half_rn(v);
    l = __float2half_rn(v - __half2float(h));
}
__device__ __forceinline__ uint32_t smem_u32(const void* p){
    uint32_t a;
    asm("{ .reg .u64 t; cvta.to.shared.u64 t, %1; cvt.u32.u64 %0, t; }" : "=r"(a) : "l"(p));
    return a;
}

// ---------------- MMA / ldmatrix / cp.async primitives (sm_80+ neutral PTX) ----------------
#define CP16(sa, ga)  asm volatile("cp.async.cg.shared.global [%0], [%1], 16;" :: "r"(sa), "l"(ga))
#define CPCOMMIT()    asm volatile("cp.async.commit_group;")
#define CPWAIT(n)     asm volatile("cp.async.wait_group %0;" :: "n"(n))

#define LDSM4(r, addr) asm volatile( \
    "ldmatrix.sync.aligned.m8n8.x4.shared.b16 {%0,%1,%2,%3}, [%4];" \
    : "=r"((r)[0]),"=r"((r)[1]),"=r"((r)[2]),"=r"((r)[3]) : "r"(addr))

#define MMA(d, a, b0v, b1v) asm volatile( \
    "mma.sync.aligned.m16n8k16.row.col.f32.f16.f16.f32 " \
    "{%0,%1,%2,%3},{%4,%5,%6,%7},{%8,%9},{%0,%1,%2,%3};" \
    : "+f"((d)[0]),"+f"((d)[1]),"+f"((d)[2]),"+f"((d)[3]) \
    : "r"((a)[0]),"r"((a)[1]),"r"((a)[2]),"r"((a)[3]),"r"(b0v),"r"(b1v))

// ============ fp16 single-pass NT GEMM: C[M,*] = A[M,384] @ B[*,384]^T ============
// tile 128x128, BK=32, 3-stage cp.async (1 sync/chunk), warp grid 2x4 (64x32 warp tiles)
// stage layout: A @0, B @10240 ; stage stride 20480 ; rows padded to 80B
// EPI 0: Cout fp32 plain
// EPI 1: f=e0h+e0l; v=acc+e1[n]*f; Cout=gelu(v)+f   (fp32)
// EPI 3: GEGLU pairs -> smem staged -> outH fp16 [BL, 384]
// EPI 4: f=e0h+e0l; o=acc+f; write Cout transposed [B,C,L] via smem staging
template<int EPI>
__global__ __launch_bounds__(256,2) void mma_gemm(
    const __half* __restrict__ Ah,
    const __half* __restrict__ Bm,
    float* __restrict__ Cout, int Nout,
    __half* __restrict__ outH,
    const __half* __restrict__ e0h, const __half* __restrict__ e0l,
    const float* __restrict__ e1)
{
    extern __shared__ char smem[];
    uint32_t sb = smem_u32(smem);
    const int tid = threadIdx.x;
    const int bm = blockIdx.y*128, bn = blockIdx.x*128;

    // ---- load indexing: rows lr, lr+64 ; seg = 16B segment within 64B row ----
    const int lr  = tid >> 2;
    const int seg = tid & 3;
    const __half* pa0 = Ah + (size_t)(bm+lr)*KDIM + seg*8;
    const __half* pb0 = Bm + (size_t)(bn+lr)*KDIM + seg*8;
    const uint32_t s0 = lr*80 + seg*16;

    // ---- compute indexing ----
    const int lane = tid & 31, w = tid >> 5;
    const int wm = (w >> 2)*64, wn = (w & 3)*32;
    const uint32_t aoff = (uint32_t)(wm + (lane & 15))*80 + (lane >> 4)*16;
    const int bg = lane >> 3, blg = lane & 7;
    const uint32_t boff = (uint32_t)(wn + (bg >> 1)*8 + blg)*80 + (bg & 1)*16;

    float acc[4][4][4];
    #pragma unroll
    for (int i=0;i<4;i++)
        #pragma unroll
        for (int j=0;j<4;j++)
            #pragma unroll
            for (int q=0;q<4;q++) acc[i][j][q]=0.f;

    auto issue = [&](int st, int kc){
        uint32_t sbase = sb + st*20480;
        #pragma unroll
        for (int h = 0; h < 2; h++){
            size_t rofs = (size_t)kc + (size_t)h*64*KDIM;
            uint32_t sa = sbase + s0 + h*64*80;
            CP16(sa,         pa0 + rofs);
            CP16(sa + 10240, pb0 + rofs);
        }
        CPCOMMIT();
    };

    issue(0, 0);
    issue(1, 32);
    int stg = 0;                        // stage of chunk c
    #pragma unroll 1
    for (int c = 0; c < 12; c++){
        if (c < 11) { CPWAIT(1); } else { CPWAIT(0); }
        __syncthreads();
        if (c + 2 < 12){
            int st2 = stg + 2; if (st2 >= 3) st2 -= 3;
            issue(st2, (c+2)*32);
        }
        uint32_t base = sb + stg*20480;
        #pragma unroll
        for (int ks = 0; ks < 2; ks++){
            uint32_t kb = ks*32;
            uint32_t a[4][4], bf[4][2], t[4];
            #pragma unroll
            for (int i=0;i<4;i++) LDSM4(a[i], base + aoff + i*16*80 + kb);
            #pragma unroll
            for (int jp=0;jp<2;jp++){
                LDSM4(t, base + 10240 + boff + jp*16*80 + kb);
                bf[2*jp][0]=t[0]; bf[2*jp][1]=t[1]; bf[2*jp+1][0]=t[2]; bf[2*jp+1][1]=t[3];
            }
            #pragma unroll
            for (int i=0;i<4;i++)
                #pragma unroll
                for (int j=0;j<4;j++) MMA(acc[i][j], a[i], bf[j][0], bf[j][1]);
        }
        if (++stg == 3) stg = 0;
    }

    // ---- epilogue ----
    const int r0 = lane >> 2, cc = (lane & 3)*2;
    if (EPI == 0 || EPI == 1){
        #pragma unroll
        for (int i=0;i<4;i++){
            int row = bm + wm + i*16 + r0;
            #pragma unroll
            for (int j=0;j<4;j++){
                int col = bn + wn + j*8 + cc;
                float v0 = acc[i][j][0], v1 = acc[i][j][1];
                float v2 = acc[i][j][2], v3 = acc[i][j][3];
                if (EPI == 1){
                    float2 d2 = *(const float2*)(e1 + col);
                    __half2 h0 = *(const __half2*)(e0h + (size_t)row*CDIM + col);
                    __half2 l0 = *(const __half2*)(e0l + (size_t)row*CDIM + col);
                    __half2 h1 = *(const __half2*)(e0h + (size_t)(row+8)*CDIM + col);
                    __half2 l1 = *(const __half2*)(e0l + (size_t)(row+8)*CDIM + col);
                    float f0x = __half2float(h0.x) + __half2float(l0.x);
                    float f0y = __half2float(h0.y) + __half2float(l0.y);
                    float f1x = __half2float(h1.x) + __half2float(l1.x);
                    float f1y = __half2float(h1.y) + __half2float(l1.y);
                    v0 = gelu_f(v0 + d2.x*f0x) + f0x;
                    v1 = gelu_f(v1 + d2.y*f0y) + f0y;
                    v2 = gelu_f(v2 + d2.x*f1x) + f1x;
                    v3 = gelu_f(v3 + d2.y*f1y) + f1y;
                }
                *(float2*)(Cout + (size_t)row*Nout + col)     = make_float2(v0, v1);
                *(float2*)(Cout + (size_t)(row+8)*Nout + col) = make_float2(v2, v3);
            }
        }
    } else if (EPI == 3){
        // GEGLU: even col = z1, odd col = z2 (interleaved W_enc); stage hi in smem
        __half* sth = (__half*)smem;    // [128 rows][72 halves stride]
        __syncthreads();
        #pragma unroll
        for (int i=0;i<4;i++){
            int rl = wm + i*16 + r0;
            #pragma unroll
            for (int j=0;j<4;j++){
                int gcl = (wn >> 1) + j*4 + (lane & 3);
                float g0 = acc[i][j][0] * gelu_f(acc[i][j][1]);
                float g1 = acc[i][j][2] * gelu_f(acc[i][j][3]);
                sth[rl*72 + gcl]     = __float2half_rn(g0);
                sth[(rl+8)*72 + gcl] = __float2half_rn(g1);
            }
        }
        __syncthreads();
        int gcol0 = bn >> 1;
        #pragma unroll
        for (int q = 0; q < 16; q++){
            int rl = w*16 + q;
            uint32_t v = *(const uint32_t*)(sth + rl*72 + 2*lane);
            *(uint32_t*)(outH + (size_t)(bm + rl)*CDIM + gcol0 + 2*lane) = v;
        }
    } else {
        // EPI 4: residual add then transposed store to [B, C, L] via smem staging
        float* smf = (float*)smem;      // [128 cols][132 row-stride]
        __syncthreads();
        #pragma unroll
        for (int i=0;i<4;i++){
            int row = bm + wm + i*16 + r0;
            int rl  = wm + i*16 + r0;
            #pragma unroll
            for (int j=0;j<4;j++){
                int col = bn + wn + j*8 + cc;
                int clo = wn + j*8 + cc;
                __half2 h0 = *(const __half2*)(e0h + (size_t)row*CDIM + col);
                __half2 l0 = *(const __half2*)(e0l + (size_t)row*CDIM + col);
                __half2 h1 = *(const __half2*)(e0h + (size_t)(row+8)*CDIM + col);
                __half2 l1 = *(const __half2*)(e0l + (size_t)(row+8)*CDIM + col);
                smf[(clo  )*132 + rl    ] = acc[i][j][0] + __half2float(h0.x) + __half2float(l0.x);
                smf[(clo+1)*132 + rl    ] = acc[i][j][1] + __half2float(h0.y) + __half2float(l0.y);
                smf[(clo  )*132 + rl + 8] = acc[i][j][2] + __half2float(h1.x) + __half2float(l1.x);
                smf[(clo+1)*132 + rl + 8] = acc[i][j][3] + __half2float(h1.y) + __half2float(l1.y);
            }
        }
        __syncthreads();
        int b  = bm >> 12;
        int l0 = bm & 4095;
        #pragma unroll
        for (int q = 0; q < 16; q++){
            int cl = w*16 + q;
            float4 v = *(const float4*)(smf + cl*132 + lane*4);
            *(float4*)(Cout + ((size_t)b*CDIM + bn + cl)*LDIM + l0 + lane*4) = v;
        }
    }
}

// ---------------- prep: discretization ----------------
__global__ void prep_lam(const float* __restrict__ Lam, const float* __restrict__ logstep){
    int p = threadIdx.x;
    float step = expf(logstep[p]);
    float lre = Lam[2*p], lim = Lam[2*p+1];
    double a  = exp((double)lre*(double)step);
    double th = (double)lim*(double)step;
    g_lam[2*p]   = (float)(a*cos(th));
    g_lam[2*p+1] = (float)(a*sin(th));
    double aT  = exp((double)TCH*(double)lre*(double)step);
    double thT = (double)TCH*th;
    g_lamT[2*p]   = (float)(aT*cos(thT));
    g_lamT[2*p+1] = (float)(aT*sin(thT));
}

__global__ void prep_wb(const float* __restrict__ Lam, const float* __restrict__ Bmat){
    int p = blockIdx.x, c = threadIdx.x;
    float lre = Lam[2*p], lim = Lam[2*p+1];
    float lbr = g_lam[2*p], lbi = g_lam[2*p+1];
    float den = lre*lre + lim*lim;
    float cr = ((lbr-1.0f)*lre + lbi*lim)/den;
    float ci = (lbi*lre - (lbr-1.0f)*lim)/den;
    float br = Bmat[(p*CDIM + c)*2], bi = Bmat[(p*CDIM + c)*2 + 1];
    g_wb[(size_t)p*CDIM + c]        = __float2half_rn(cr*br - ci*bi);
    g_wb[(size_t)(PDIM+p)*CDIM + c] = __float2half_rn(cr*bi + ci*br);
}

__global__ void prep_wc(const float* __restrict__ Lam, const float* __restrict__ logstep,
                        const float* __restrict__ Cmat){
    int hrow = blockIdx.x, p = threadIdx.x;
    float step = expf(logstep[p]);
    float lim = Lam[2*p+1];
    float freq = step*fabsf(lim)*(float)(1.0/(2.0*3.14159265358979323846));
    float m = (freq < 0.25f) ? 2.0f : 0.0f;
    float cre = Cmat[(hrow*PDIM + p)*2], cim = Cmat[(hrow*PDIM + p)*2 + 1];
    g_wc[(size_t)hrow*CDIM + p]        = __float2half_rn( m*cre);
    g_wc[(size_t)hrow*CDIM + PDIM + p] = __float2half_rn(-m*cim);
}

// interleave W_enc rows: out row 2t = z1 row t, out row 2t+1 = z2 row (384+t)
__global__ void prep_we(const float* __restrict__ Wenc, __half* __restrict__ we){
    int n = blockIdx.x, c = threadIdx.x;
    int src = (n & 1) ? (CDIM + (n >> 1)) : (n >> 1);
    we[(size_t)n*CDIM + c] = __float2half_rn(Wenc[(size_t)src*CDIM + c]);
}

__global__ void cvt_h(const float* __restrict__ src, __half* __restrict__ h, int n){
    int i = blockIdx.x*blockDim.x + threadIdx.x;
    if (i < n) h[i] = __float2half_rn(src[i]);
}

// ---------------- LayerNorm 1 : x[B,C,L] -> hi/lo fp16 [BL,C] ----------------
__global__ __launch_bounds__(256) void ln1_kernel(const float* __restrict__ x,
                                                  const float* __restrict__ gam,
                                                  const float* __restrict__ bet,
                                                  __half* __restrict__ fxh,
                                                  __half* __restrict__ fxl){
    __shared__ float tile[CDIM][17];
    int b = blockIdx.y, l0 = blockIdx.x*16;
    int tid = threadIdx.x;
    for (int idx = tid; idx < CDIM*16; idx += 256){
        int c = idx >> 4, j = idx & 15;
        tile[c][j] = x[((size_t)b*CDIM + c)*LDIM + l0 + j];
    }
    __syncthreads();
    int w = tid >> 5, lane = tid & 31;
    for (int j = w*2; j < w*2 + 2; j++){
        float v[12]; float s = 0.0f;
        #pragma unroll
        for (int k = 0; k < 12; k++){ v[k] = tile[lane + 32*k][j]; s += v[k]; }
        #pragma unroll
        for (int o = 16; o; o >>= 1) s += __shfl_xor_sync(0xffffffffu, s, o);
        float mu = s * (1.0f/CDIM);
        float q = 0.0f;
        #pragma unroll
        for (int k = 0; k < 12; k++){ float d = v[k]-mu; q += d*d; }
        #pragma unroll
        for (int o = 16; o; o >>= 1) q += __shfl_xor_sync(0xffffffffu, q, o);
        float inv = rsqrtf(q*(1.0f/CDIM) + 1e-5f);
        size_t row = ((size_t)b*LDIM + l0 + j)*CDIM;
        #pragma unroll
        for (int k = 0; k < 12; k++){
            int c = lane + 32*k;
            float val = (v[k]-mu)*inv*gam[c] + bet[c];
            __half h,l; split_hl(val,h,l);
            fxh[row + c] = h; fxl[row + c] = l;
        }
    }
}

// ---------------- LayerNorm 2 : y[BL,C] -> hi/lo ----------------
__global__ __launch_bounds__(256) void ln2_kernel(const float* __restrict__ y,
                                                  const float* __restrict__ gam,
                                                  const float* __restrict__ bet,
                                                  __half* __restrict__ fyh,
                                                  __half* __restrict__ fyl){
    int row = blockIdx.x*8 + (threadIdx.x >> 5);
    int lane = threadIdx.x & 31;
    const float4* r4 = (const float4*)(y + (size_t)row*CDIM);
    float4 v[3]; float s = 0.0f;
    #pragma unroll
    for (int k = 0; k < 3; k++){ v[k] = r4[lane + 32*k]; s += v[k].x+v[k].y+v[k].z+v[k].w; }
    #pragma unroll
    for (int o = 16; o; o >>= 1) s += __shfl_xor_sync(0xffffffffu, s, o);
    float mu = s * (1.0f/CDIM);
    float q = 0.0f;
    #pragma unroll
    for (int k = 0; k < 3; k++){
        float dx=v[k].x-mu, dy=v[k].y-mu, dz=v[k].z-mu, dw=v[k].w-mu;
        q += dx*dx+dy*dy+dz*dz+dw*dw;
    }
    #pragma unroll
    for (int o = 16; o; o >>= 1) q += __shfl_xor_sync(0xffffffffu, q, o);
    float inv = rsqrtf(q*(1.0f/CDIM) + 1e-5f);
    #pragma unroll
    for (int k = 0; k < 3; k++){
        int c4 = lane + 32*k;
        float4 gg = ((const float4*)gam)[c4], bb = ((const float4*)bet)[c4];
        float rx = (v[k].x-mu)*inv*gg.x + bb.x;
        float ry = (v[k].y-mu)*inv*gg.y + bb.y;
        float rz = (v[k].z-mu)*inv*gg.z + bb.z;
        float rw = (v[k].w-mu)*inv*gg.w + bb.w;
        size_t base = (size_t)row*CDIM + c4*4;
        __half h,l;
        split_hl(rx,h,l); fyh[base+0]=h; fyl[base+0]=l;
        split_hl(ry,h,l); fyh[base+1]=h; fyl[base+1]=l;
        split_hl(rz,h,l); fyh[base+2]=h; fyl[base+2]=l;
        split_hl(rw,h,l); fyh[base+3]=h; fyl[base+3]=l;
    }
}

// ---------------- chunked constant-coefficient complex scan ----------------
__global__ void scan_a(const float* __restrict__ bu, float* __restrict__ carry){
    int p = threadIdx.x, ch = blockIdx.x, b = blockIdx.y;
    float lre = g_lam[2*p], lim = g_lam[2*p+1];
    float sre = 0.0f, sim = 0.0f;
    size_t base = ((size_t)b*LDIM + (size_t)ch*TCH)*CDIM;
    for (int i = 0; i < TCH; i++){
        size_t idx = base + (size_t)i*CDIM;
        float br = bu[idx+p], bi = bu[idx+PDIM+p];
        float nr = fmaf(lre, sre, fmaf(-lim, sim, br));
        float ni = fmaf(lre, sim, fmaf( lim, sre, bi));
        sre = nr; sim = ni;
    }
    size_t cidx = ((size_t)b*NCH + ch)*CDIM;
    carry[cidx+p] = sre; carry[cidx+PDIM+p] = sim;
}

__global__ void scan_b(float* __restrict__ carry){
    int p = threadIdx.x, b = blockIdx.x;
    float tr = g_lamT[2*p], ti = g_lamT[2*p+1];
    float pr = 0.0f, pi = 0.0f;
    for (int k = 0; k < NCH; k++){
        size_t ci = ((size_t)b*NCH + k)*CDIM;
        float cr = carry[ci+p], cm = carry[ci+PDIM+p];
        carry[ci+p] = pr; carry[ci+PDIM+p] = pi;      // exclusive prefix
        float nr = fmaf(tr, pr, fmaf(-ti, pi, cr));
        float ni = fmaf(tr, pi, fmaf( ti, pr, cm));
        pr = nr; pi = ni;
    }
}

// scan_c: full local recurrence seeded by carry prefix; emit xs fp16 (hi only)
__global__ void scan_c(const float* __restrict__ bu, const float* __restrict__ carry,
                       __half* __restrict__ bh){
    int p = threadIdx.x, ch = blockIdx.x, b = blockIdx.y;
    size_t cidx = ((size_t)b*NCH + ch)*CDIM;
    float sre = carry[cidx+p], sim = carry[cidx+PDIM+p];   // ch==0 prefix is 0
    float lre = g_lam[2*p], lim = g_lam[2*p+1];
    size_t base = ((size_t)b*LDIM + (size_t)ch*TCH)*CDIM;
    for (int i = 0; i < TCH; i++){
        size_t idx = base + (size_t)i*CDIM;
        float br = bu[idx+p], bi = bu[idx+PDIM+p];
        float nr = fmaf(lre, sre, fmaf(-lim, sim, br));
        float ni = fmaf(lre, sim, fmaf( lim, sre, bi));
        sre = nr; sim = ni;
        bh[idx+p]      = __float2half_rn(nr);
        bh[idx+PDIM+p] = __float2half_rn(ni);
    }
}

// ---------------- launch ----------------
extern "C" void kernel_launch(void* const* d_in, const int* in_sizes, int n_in,
                              void* d_out, int out_size){
    const float* x       = (const float*)d_in[0];
    const float* ln1g    = (const float*)d_in[1];
    const float* ln1b    = (const float*)d_in[2];
    const float* Lam     = (const float*)d_in[3];
    const float* Bmat    = (const float*)d_in[4];
    const float* Cmat    = (const float*)d_in[5];
    const float* Dv      = (const float*)d_in[6];
    const float* logstep = (const float*)d_in[7];
    const float* ln2g    = (const float*)d_in[8];
    const float* ln2b    = (const float*)d_in[9];
    const float* Wenc    = (const float*)d_in[10];
    const float* Wdec    = (const float*)d_in[11];
    float* out = (float*)d_out;

    float *bu,*y,*carry;
    cudaGetSymbolAddress((void**)&bu,    g_bu);
    cudaGetSymbolAddress((void**)&y,     g_y);
    cudaGetSymbolAddress((void**)&carry, g_carry);

    __half *fxh,*fxl,*buh,*fyh,*fyl,*ggh,*wb,*wc,*we,*wd;
    cudaGetSymbolAddress((void**)&fxh, g_fxh); cudaGetSymbolAddress((void**)&fxl, g_fxl);
    cudaGetSymbolAddress((void**)&buh, g_buh);
    cudaGetSymbolAddress((void**)&fyh, g_fyh); cudaGetSymbolAddress((void**)&fyl, g_fyl);
    cudaGetSymbolAddress((void**)&ggh, g_ggh);
    cudaGetSymbolAddress((void**)&wb,  g_wb);  cudaGetSymbolAddress((void**)&wc,  g_wc);
    cudaGetSymbolAddress((void**)&we,  g_we);  cudaGetSymbolAddress((void**)&wd,  g_wd);

    const int SMEM_GEMM = 3*20480 + 8192;   // 69632 B (3-stage + EPI staging headroom)
    cudaFuncSetAttribute(mma_gemm<0>, cudaFuncAttributeMaxDynamicSharedMemorySize, SMEM_GEMM);
    cudaFuncSetAttribute(mma_gemm<1>, cudaFuncAttributeMaxDynamicSharedMemorySize, SMEM_GEMM);
    cudaFuncSetAttribute(mma_gemm<3>, cudaFuncAttributeMaxDynamicSharedMemorySize, SMEM_GEMM);
    cudaFuncSetAttribute(mma_gemm<4>, cudaFuncAttributeMaxDynamicSharedMemorySize, SMEM_GEMM);

    prep_lam<<<1, PDIM>>>(Lam, logstep);
    prep_wb<<<PDIM, CDIM>>>(Lam, Bmat);
    prep_wc<<<CDIM, PDIM>>>(Lam, logstep, Cmat);
    prep_we<<<2*CDIM, CDIM>>>(Wenc, we);
    cvt_h<<<(CDIM*CDIM + 255)/256, 256>>>(Wdec, wd, CDIM*CDIM);

    ln1_kernel<<<dim3(LDIM/16, BSZ), 256>>>(x, ln1g, ln1b, fxh, fxl);

    // Bu = fx @ Bbar_packed^T   -> [BL, 2P] fp32
    mma_gemm<0><<<dim3(3, 512), 256, SMEM_GEMM>>>(fxh, wb, bu, CDIM,
                                                  nullptr, nullptr, nullptr, nullptr);

    scan_a<<<dim3(NCH, BSZ), PDIM>>>(bu, carry);
    scan_b<<<BSZ, PDIM>>>(carry);
    scan_c<<<dim3(NCH, BSZ), PDIM>>>(bu, carry, buh);

    // y = gelu(xs @ Ceff^T + D*fx) + fx
    mma_gemm<1><<<dim3(3, 512), 256, SMEM_GEMM>>>(buh, wc, y, CDIM,
                                                  nullptr, fxh, fxl, Dv);

    ln2_kernel<<<BLTOK/8, 256>>>(y, ln2g, ln2b, fyh, fyl);

    // gg = GEGLU(fy @ Wenc_interleaved^T)  -> fp16 [BL, 384] directly
    mma_gemm<3><<<dim3(6, 512), 256, SMEM_GEMM>>>(fyh, we, nullptr, CDIM,
                                                  ggh, nullptr, nullptr, nullptr);

    // out = transpose(gg @ Wdec^T + fy)  (written straight to [B,C,L])
    mma_gemm<4><<<dim3(3, 512), 256, SMEM_GEMM>>>(ggh, wd, out, CDIM,
                                                  nullptr, fyh, fyl, nullptr);
}

// round 8
// speedup vs baseline: 4.4400x; 1.0379x over previous
#include <cuda_runtime.h>
#include <cuda_fp16.h>
#include <math.h>
#include <stdint.h>

#define BSZ  16
#define CDIM 384
#define LDIM 4096
#define PDIM 192
#define BLTOK (BSZ*LDIM)      // 65536
#define NCH  64
#define TCH  64
#define KDIM 384

// ---------------- static scratch (no allocations allowed) ----------------
__device__ float g_y [(size_t)BLTOK*CDIM];
__device__ float g_lam [2*PDIM];
__device__ float g_lamT[2*PDIM];
__device__ float g_carry[(size_t)BSZ*NCH*CDIM];

// fp16 operands; lo-arrays only where an epilogue residual needs full accuracy
__device__ __half g_buf[(size_t)BLTOK*CDIM];   // Bu fp16 (pre-scan)
__device__ __half g_fxh[(size_t)BLTOK*CDIM], g_fxl[(size_t)BLTOK*CDIM];
__device__ __half g_buh[(size_t)BLTOK*CDIM];   // xs fp16 (post-scan)
__device__ __half g_fyh[(size_t)BLTOK*CDIM], g_fyl[(size_t)BLTOK*CDIM];
__device__ __half g_ggh[(size_t)BLTOK*CDIM];
__device__ __half g_wb[CDIM*CDIM];
__device__ __half g_wc[CDIM*CDIM];
__device__ __half g_we[2*CDIM*CDIM];   // interleaved z1/z2 rows
__device__ __half g_wd[CDIM*CDIM];

__device__ __forceinline__ float gelu_f(float v){
    return 0.5f*v*(1.0f + erff(v*0.70710678118654752f));
}
__device__ __forceinline__ void split_hl(float v, __half& h, __half& l){
    h = __float2half_rn(v);
    l = __float2half_rn(v - __half2float(h));
}
__device__ __forceinline__ uint32_t smem_u32(const void* p){
    uint32_t a;
    asm("{ .reg .u64 t; cvta.to.shared.u64 t, %1; cvt.u32.u64 %0, t; }" : "=r"(a) : "l"(p));
    return a;
}

// ---------------- MMA / ldmatrix / cp.async primitives (sm_80+ neutral PTX) ----------------
#define CP16(sa, ga)  asm volatile("cp.async.cg.shared.global [%0], [%1], 16;" :: "r"(sa), "l"(ga))
#define CPCOMMIT()    asm volatile("cp.async.commit_group;")
#define CPWAIT(n)     asm volatile("cp.async.wait_group %0;" :: "n"(n))

#define LDSM4(r, addr) asm volatile( \
    "ldmatrix.sync.aligned.m8n8.x4.shared.b16 {%0,%1,%2,%3}, [%4];" \
    : "=r"((r)[0]),"=r"((r)[1]),"=r"((r)[2]),"=r"((r)[3]) : "r"(addr))

#define MMA(d, a, b0v, b1v) asm volatile( \
    "mma.sync.aligned.m16n8k16.row.col.f32.f16.f16.f32 " \
    "{%0,%1,%2,%3},{%4,%5,%6,%7},{%8,%9},{%0,%1,%2,%3};" \
    : "+f"((d)[0]),"+f"((d)[1]),"+f"((d)[2]),"+f"((d)[3]) \
    : "r"((a)[0]),"r"((a)[1]),"r"((a)[2]),"r"((a)[3]),"r"(b0v),"r"(b1v))

// ============ fp16 single-pass NT GEMM: C[M,*] = A[M,384] @ B[*,384]^T ============
// tile 128x128, BK=32, 3-stage cp.async (1 sync/chunk), warp grid 2x4 (64x32 warp tiles)
// stage layout: A @0, B @10240 ; stage stride 20480 ; rows padded to 80B
// EPI 1: f=e0h+e0l; v=acc+e1[n]*f; Cout=gelu(v)+f   (fp32)
// EPI 3: GEGLU pairs -> smem staged -> outH fp16 [BL, 384]
// EPI 4: f=e0h+e0l; o=acc+f; write Cout transposed [B,C,L] via smem staging
// EPI 5: plain fp16 out -> outH
template<int EPI>
__global__ __launch_bounds__(256,2) void mma_gemm(
    const __half* __restrict__ Ah,
    const __half* __restrict__ Bm,
    float* __restrict__ Cout, int Nout,
    __half* __restrict__ outH,
    const __half* __restrict__ e0h, const __half* __restrict__ e0l,
    const float* __restrict__ e1)
{
    extern __shared__ char smem[];
    uint32_t sb = smem_u32(smem);
    const int tid = threadIdx.x;
    const int bm = blockIdx.y*128, bn = blockIdx.x*128;

    // ---- load indexing: rows lr, lr+64 ; seg = 16B segment within 64B row ----
    const int lr  = tid >> 2;
    const int seg = tid & 3;
    const __half* pa0 = Ah + (size_t)(bm+lr)*KDIM + seg*8;
    const __half* pb0 = Bm + (size_t)(bn+lr)*KDIM + seg*8;
    const uint32_t s0 = lr*80 + seg*16;

    // ---- compute indexing ----
    const int lane = tid & 31, w = tid >> 5;
    const int wm = (w >> 2)*64, wn = (w & 3)*32;
    const uint32_t aoff = (uint32_t)(wm + (lane & 15))*80 + (lane >> 4)*16;
    const int bg = lane >> 3, blg = lane & 7;
    const uint32_t boff = (uint32_t)(wn + (bg >> 1)*8 + blg)*80 + (bg & 1)*16;

    float acc[4][4][4];
    #pragma unroll
    for (int i=0;i<4;i++)
        #pragma unroll
        for (int j=0;j<4;j++)
            #pragma unroll
            for (int q=0;q<4;q++) acc[i][j][q]=0.f;

    auto issue = [&](int st, int kc){
        uint32_t sbase = sb + st*20480;
        #pragma unroll
        for (int h = 0; h < 2; h++){
            size_t rofs = (size_t)kc + (size_t)h*64*KDIM;
            uint32_t sa = sbase + s0 + h*64*80;
            CP16(sa,         pa0 + rofs);
            CP16(sa + 10240, pb0 + rofs);
        }
        CPCOMMIT();
    };

    issue(0, 0);
    issue(1, 32);
    int stg = 0;                        // stage of chunk c
    #pragma unroll 1
    for (int c = 0; c < 12; c++){
        if (c < 11) { CPWAIT(1); } else { CPWAIT(0); }
        __syncthreads();
        if (c + 2 < 12){
            int st2 = stg + 2; if (st2 >= 3) st2 -= 3;
            issue(st2, (c+2)*32);
        }
        uint32_t base = sb + stg*20480;
        #pragma unroll
        for (int ks = 0; ks < 2; ks++){
            uint32_t kb = ks*32;
            uint32_t a[4][4], bf[4][2], t[4];
            #pragma unroll
            for (int i=0;i<4;i++) LDSM4(a[i], base + aoff + i*16*80 + kb);
            #pragma unroll
            for (int jp=0;jp<2;jp++){
                LDSM4(t, base + 10240 + boff + jp*16*80 + kb);
                bf[2*jp][0]=t[0]; bf[2*jp][1]=t[1]; bf[2*jp+1][0]=t[2]; bf[2*jp+1][1]=t[3];
            }
            #pragma unroll
            for (int i=0;i<4;i++)
                #pragma unroll
                for (int j=0;j<4;j++) MMA(acc[i][j], a[i], bf[j][0], bf[j][1]);
        }
        if (++stg == 3) stg = 0;
    }

    // ---- epilogue ----
    const int r0 = lane >> 2, cc = (lane & 3)*2;
    if (EPI == 1){
        #pragma unroll
        for (int i=0;i<4;i++){
            int row = bm + wm + i*16 + r0;
            #pragma unroll
            for (int j=0;j<4;j++){
                int col = bn + wn + j*8 + cc;
                float v0 = acc[i][j][0], v1 = acc[i][j][1];
                float v2 = acc[i][j][2], v3 = acc[i][j][3];
                float2 d2 = *(const float2*)(e1 + col);
                __half2 h0 = *(const __half2*)(e0h + (size_t)row*CDIM + col);
                __half2 l0 = *(const __half2*)(e0l + (size_t)row*CDIM + col);
                __half2 h1 = *(const __half2*)(e0h + (size_t)(row+8)*CDIM + col);
                __half2 l1 = *(const __half2*)(e0l + (size_t)(row+8)*CDIM + col);
                float f0x = __half2float(h0.x) + __half2float(l0.x);
                float f0y = __half2float(h0.y) + __half2float(l0.y);
                float f1x = __half2float(h1.x) + __half2float(l1.x);
                float f1y = __half2float(h1.y) + __half2float(l1.y);
                v0 = gelu_f(v0 + d2.x*f0x) + f0x;
                v1 = gelu_f(v1 + d2.y*f0y) + f0y;
                v2 = gelu_f(v2 + d2.x*f1x) + f1x;
                v3 = gelu_f(v3 + d2.y*f1y) + f1y;
                *(float2*)(Cout + (size_t)row*Nout + col)     = make_float2(v0, v1);
                *(float2*)(Cout + (size_t)(row+8)*Nout + col) = make_float2(v2, v3);
            }
        }
    } else if (EPI == 3){
        // GEGLU: even col = z1, odd col = z2 (interleaved W_enc); stage hi in smem
        __half* sth = (__half*)smem;    // [128 rows][72 halves stride]
        __syncthreads();
        #pragma unroll
        for (int i=0;i<4;i++){
            int rl = wm + i*16 + r0;
            #pragma unroll
            for (int j=0;j<4;j++){
                int gcl = (wn >> 1) + j*4 + (lane & 3);
                float g0 = acc[i][j][0] * gelu_f(acc[i][j][1]);
                float g1 = acc[i][j][2] * gelu_f(acc[i][j][3]);
                sth[rl*72 + gcl]     = __float2half_rn(g0);
                sth[(rl+8)*72 + gcl] = __float2half_rn(g1);
            }
        }
        __syncthreads();
        int gcol0 = bn >> 1;
        #pragma unroll
        for (int q = 0; q < 16; q++){
            int rl = w*16 + q;
            uint32_t v = *(const uint32_t*)(sth + rl*72 + 2*lane);
            *(uint32_t*)(outH + (size_t)(bm + rl)*CDIM + gcol0 + 2*lane) = v;
        }
    } else if (EPI == 4){
        // residual add then transposed store to [B, C, L] via smem staging
        float* smf = (float*)smem;      // [128 cols][132 row-stride]
        __syncthreads();
        #pragma unroll
        for (int i=0;i<4;i++){
            int row = bm + wm + i*16 + r0;
            int rl  = wm + i*16 + r0;
            #pragma unroll
            for (int j=0;j<4;j++){
                int col = bn + wn + j*8 + cc;
                int clo = wn + j*8 + cc;
                __half2 h0 = *(const __half2*)(e0h + (size_t)row*CDIM + col);
                __half2 l0 = *(const __half2*)(e0l + (size_t)row*CDIM + col);
                __half2 h1 = *(const __half2*)(e0h + (size_t)(row+8)*CDIM + col);
                __half2 l1 = *(const __half2*)(e0l + (size_t)(row+8)*CDIM + col);
                smf[(clo  )*132 + rl    ] = acc[i][j][0] + __half2float(h0.x) + __half2float(l0.x);
                smf[(clo+1)*132 + rl    ] = acc[i][j][1] + __half2float(h0.y) + __half2float(l0.y);
                smf[(clo  )*132 + rl + 8] = acc[i][j][2] + __half2float(h1.x) + __half2float(l1.x);
                smf[(clo+1)*132 + rl + 8] = acc[i][j][3] + __half2float(h1.y) + __half2float(l1.y);
            }
        }
        __syncthreads();
        int b  = bm >> 12;
        int l0 = bm & 4095;
        #pragma unroll
        for (int q = 0; q < 16; q++){
            int cl = w*16 + q;
            float4 v = *(const float4*)(smf + cl*132 + lane*4);
            *(float4*)(Cout + ((size_t)b*CDIM + bn + cl)*LDIM + l0 + lane*4) = v;
        }
    } else {
        // EPI 5: plain fp16 store
        #pragma unroll
        for (int i=0;i<4;i++){
            int row = bm + wm + i*16 + r0;
            #pragma unroll
            for (int j=0;j<4;j++){
                int col = bn + wn + j*8 + cc;
                __half2 v01 = __floats2half2_rn(acc[i][j][0], acc[i][j][1]);
                __half2 v23 = __floats2half2_rn(acc[i][j][2], acc[i][j][3]);
                *(__half2*)(outH + (size_t)row*Nout + col)     = v01;
                *(__half2*)(outH + (size_t)(row+8)*Nout + col) = v23;
            }
        }
    }
}

// ---------------- prep: discretization (must run first; others read g_lam) ----------------
__global__ void prep_lam(const float* __restrict__ Lam, const float* __restrict__ logstep){
    int p = threadIdx.x;
    float step = expf(logstep[p]);
    float lre = Lam[2*p], lim = Lam[2*p+1];
    double a  = exp((double)lre*(double)step);
    double th = (double)lim*(double)step;
    g_lam[2*p]   = (float)(a*cos(th));
    g_lam[2*p+1] = (float)(a*sin(th));
    double aT  = exp((double)TCH*(double)lre*(double)step);
    double thT = (double)TCH*th;
    g_lamT[2*p]   = (float)(aT*cos(thT));
    g_lamT[2*p+1] = (float)(aT*sin(thT));
}

// one kernel for all weight preps: wb(192) | wc(384) | we(768) | wd(384) blocks
__global__ void prep_all(const float* __restrict__ Lam, const float* __restrict__ logstep,
                         const float* __restrict__ Bmat, const float* __restrict__ Cmat,
                         const float* __restrict__ Wenc, const float* __restrict__ Wdec){
    int bid = blockIdx.x, tid = threadIdx.x;
    if (bid < 192){
        int p = bid, c = tid;
        float lre = Lam[2*p], lim = Lam[2*p+1];
        float lbr = g_lam[2*p], lbi = g_lam[2*p+1];
        float den = lre*lre + lim*lim;
        float cr = ((lbr-1.0f)*lre + lbi*lim)/den;
        float ci = (lbi*lre - (lbr-1.0f)*lim)/den;
        float br = Bmat[(p*CDIM + c)*2], bi = Bmat[(p*CDIM + c)*2 + 1];
        g_wb[(size_t)p*CDIM + c]        = __float2half_rn(cr*br - ci*bi);
        g_wb[(size_t)(PDIM+p)*CDIM + c] = __float2half_rn(cr*bi + ci*br);
    } else if (bid < 576){
        if (tid < PDIM){
            int hrow = bid - 192, p = tid;
            float step = expf(logstep[p]);
            float lim = Lam[2*p+1];
            float freq = step*fabsf(lim)*(float)(1.0/(2.0*3.14159265358979323846));
            float m = (freq < 0.25f) ? 2.0f : 0.0f;
            float cre = Cmat[(hrow*PDIM + p)*2], cim = Cmat[(hrow*PDIM + p)*2 + 1];
            g_wc[(size_t)hrow*CDIM + p]        = __float2half_rn( m*cre);
            g_wc[(size_t)hrow*CDIM + PDIM + p] = __float2half_rn(-m*cim);
        }
    } else if (bid < 1344){
        int n = bid - 576, c = tid;
        int src = (n & 1) ? (CDIM + (n >> 1)) : (n >> 1);
        g_we[(size_t)n*CDIM + c] = __float2half_rn(Wenc[(size_t)src*CDIM + c]);
    } else {
        int i = (bid - 1344)*CDIM + tid;   // 384 blocks x 384 = 147456 exactly
        g_wd[i] = __float2half_rn(Wdec[i]);
    }
}

// ---------------- LayerNorm 1 : x[B,C,L] -> hi/lo fp16 [BL,C] ----------------
__global__ __launch_bounds__(256) void ln1_kernel(const float* __restrict__ x,
                                                  const float* __restrict__ gam,
                                                  const float* __restrict__ bet,
                                                  __half* __restrict__ fxh,
                                                  __half* __restrict__ fxl){
    __shared__ float tile[CDIM][17];
    int b = blockIdx.y, l0 = blockIdx.x*16;
    int tid = threadIdx.x;
    for (int idx = tid; idx < CDIM*16; idx += 256){
        int c = idx >> 4, j = idx & 15;
        tile[c][j] = x[((size_t)b*CDIM + c)*LDIM + l0 + j];
    }
    __syncthreads();
    int w = tid >> 5, lane = tid & 31;
    for (int j = w*2; j < w*2 + 2; j++){
        float v[12]; float s = 0.0f;
        #pragma unroll
        for (int k = 0; k < 12; k++){ v[k] = tile[lane + 32*k][j]; s += v[k]; }
        #pragma unroll
        for (int o = 16; o; o >>= 1) s += __shfl_xor_sync(0xffffffffu, s, o);
        float mu = s * (1.0f/CDIM);
        float q = 0.0f;
        #pragma unroll
        for (int k = 0; k < 12; k++){ float d = v[k]-mu; q += d*d; }
        #pragma unroll
        for (int o = 16; o; o >>= 1) q += __shfl_xor_sync(0xffffffffu, q, o);
        float inv = rsqrtf(q*(1.0f/CDIM) + 1e-5f);
        size_t row = ((size_t)b*LDIM + l0 + j)*CDIM;
        #pragma unroll
        for (int k = 0; k < 12; k++){
            int c = lane + 32*k;
            float val = (v[k]-mu)*inv*gam[c] + bet[c];
            __half h,l; split_hl(val,h,l);
            fxh[row + c] = h; fxl[row + c] = l;
        }
    }
}

// ---------------- LayerNorm 2 : y[BL,C] -> hi/lo ----------------
__global__ __launch_bounds__(256) void ln2_kernel(const float* __restrict__ y,
                                                  const float* __restrict__ gam,
                                                  const float* __restrict__ bet,
                                                  __half* __restrict__ fyh,
                                                  __half* __restrict__ fyl){
    int row = blockIdx.x*8 + (threadIdx.x >> 5);
    int lane = threadIdx.x & 31;
    const float4* r4 = (const float4*)(y + (size_t)row*CDIM);
    float4 v[3]; float s = 0.0f;
    #pragma unroll
    for (int k = 0; k < 3; k++){ v[k] = r4[lane + 32*k]; s += v[k].x+v[k].y+v[k].z+v[k].w; }
    #pragma unroll
    for (int o = 16; o; o >>= 1) s += __shfl_xor_sync(0xffffffffu, s, o);
    float mu = s * (1.0f/CDIM);
    float q = 0.0f;
    #pragma unroll
    for (int k = 0; k < 3; k++){
        float dx=v[k].x-mu, dy=v[k].y-mu, dz=v[k].z-mu, dw=v[k].w-mu;
        q += dx*dx+dy*dy+dz*dz+dw*dw;
    }
    #pragma unroll
    for (int o = 16; o; o >>= 1) q += __shfl_xor_sync(0xffffffffu, q, o);
    float inv = rsqrtf(q*(1.0f/CDIM) + 1e-5f);
    #pragma unroll
    for (int k = 0; k < 3; k++){
        int c4 = lane + 32*k;
        float4 gg = ((const float4*)gam)[c4], bb = ((const float4*)bet)[c4];
        float rx = (v[k].x-mu)*inv*gg.x + bb.x;
        float ry = (v[k].y-mu)*inv*gg.y + bb.y;
        float rz = (v[k].z-mu)*inv*gg.z + bb.z;
        float rw = (v[k].w-mu)*inv*gg.w + bb.w;
        size_t base = (size_t)row*CDIM + c4*4;
        __half h,l;
        split_hl(rx,h,l); fyh[base+0]=h; fyl[base+0]=l;
        split_hl(ry,h,l); fyh[base+1]=h; fyl[base+1]=l;
        split_hl(rz,h,l); fyh[base+2]=h; fyl[base+2]=l;
        split_hl(rw,h,l); fyh[base+3]=h; fyl[base+3]=l;
    }
}

// ---------------- chunked constant-coefficient complex scan (fp16 Bu) ----------------
__global__ void scan_a(const __half* __restrict__ bu, float* __restrict__ carry){
    int p = threadIdx.x, ch = blockIdx.x, b = blockIdx.y;
    float lre = g_lam[2*p], lim = g_lam[2*p+1];
    float sre = 0.0f, sim = 0.0f;
    size_t base = ((size_t)b*LDIM + (size_t)ch*TCH)*CDIM;
    for (int i = 0; i < TCH; i++){
        size_t idx = base + (size_t)i*CDIM;
        float br = __half2float(bu[idx+p]), bi = __half2float(bu[idx+PDIM+p]);
        float nr = fmaf(lre, sre, fmaf(-lim, sim, br));
        float ni = fmaf(lre, sim, fmaf( lim, sre, bi));
        sre = nr; sim = ni;
    }
    size_t cidx = ((size_t)b*NCH + ch)*CDIM;
    carry[cidx+p] = sre; carry[cidx+PDIM+p] = sim;
}

// scan_c: compose prefix from raw carries (scan_b folded in), run local recurrence, emit fp16
__global__ void scan_c(const __half* __restrict__ bu, const float* __restrict__ carry,
                       __half* __restrict__ bh){
    int p = threadIdx.x, ch = blockIdx.x, b = blockIdx.y;
    float tr = g_lamT[2*p], ti = g_lamT[2*p+1];
    float sre = 0.0f, sim = 0.0f;
    for (int k = 0; k < ch; k++){
        size_t ci = ((size_t)b*NCH + k)*CDIM;
        float cr = carry[ci+p], cm = carry[ci+PDIM+p];
        float nr = fmaf(tr, sre, fmaf(-ti, sim, cr));
        float ni = fmaf(tr, sim, fmaf( ti, sre, cm));
        sre = nr; sim = ni;
    }
    float lre = g_lam[2*p], lim = g_lam[2*p+1];
    size_t base = ((size_t)b*LDIM + (size_t)ch*TCH)*CDIM;
    for (int i = 0; i < TCH; i++){
        size_t idx = base + (size_t)i*CDIM;
        float br = __half2float(bu[idx+p]), bi = __half2float(bu[idx+PDIM+p]);
        float nr = fmaf(lre, sre, fmaf(-lim, sim, br));
        float ni = fmaf(lre, sim, fmaf( lim, sre, bi));
        sre = nr; sim = ni;
        bh[idx+p]      = __float2half_rn(nr);
        bh[idx+PDIM+p] = __float2half_rn(ni);
    }
}

// ---------------- launch ----------------
extern "C" void kernel_launch(void* const* d_in, const int* in_sizes, int n_in,
                              void* d_out, int out_size){
    const float* x       = (const float*)d_in[0];
    const float* ln1g    = (const float*)d_in[1];
    const float* ln1b    = (const float*)d_in[2];
    const float* Lam     = (const float*)d_in[3];
    const float* Bmat    = (const float*)d_in[4];
    const float* Cmat    = (const float*)d_in[5];
    const float* Dv      = (const float*)d_in[6];
    const float* logstep = (const float*)d_in[7];
    const float* ln2g    = (const float*)d_in[8];
    const float* ln2b    = (const float*)d_in[9];
    const float* Wenc    = (const float*)d_in[10];
    const float* Wdec    = (const float*)d_in[11];
    float* out = (float*)d_out;

    float *y,*carry;
    cudaGetSymbolAddress((void**)&y,     g_y);
    cudaGetSymbolAddress((void**)&carry, g_carry);

    __half *buf,*fxh,*fxl,*buh,*fyh,*fyl,*ggh,*wb,*wc,*we,*wd;
    cudaGetSymbolAddress((void**)&buf, g_buf);
    cudaGetSymbolAddress((void**)&fxh, g_fxh); cudaGetSymbolAddress((void**)&fxl, g_fxl);
    cudaGetSymbolAddress((void**)&buh, g_buh);
    cudaGetSymbolAddress((void**)&fyh, g_fyh); cudaGetSymbolAddress((void**)&fyl, g_fyl);
    cudaGetSymbolAddress((void**)&ggh, g_ggh);
    cudaGetSymbolAddress((void**)&wb,  g_wb);  cudaGetSymbolAddress((void**)&wc,  g_wc);
    cudaGetSymbolAddress((void**)&we,  g_we);  cudaGetSymbolAddress((void**)&wd,  g_wd);

    const int SMEM_GEMM = 3*20480 + 8192;   // 69632 B (3-stage + EPI staging headroom)
    cudaFuncSetAttribute(mma_gemm<1>, cudaFuncAttributeMaxDynamicSharedMemorySize, SMEM_GEMM);
    cudaFuncSetAttribute(mma_gemm<3>, cudaFuncAttributeMaxDynamicSharedMemorySize, SMEM_GEMM);
    cudaFuncSetAttribute(mma_gemm<4>, cudaFuncAttributeMaxDynamicSharedMemorySize, SMEM_GEMM);
    cudaFuncSetAttribute(mma_gemm<5>, cudaFuncAttributeMaxDynamicSharedMemorySize, SMEM_GEMM);

    // launch 1-2: prep
    prep_lam<<<1, PDIM>>>(Lam, logstep);
    prep_all<<<1728, CDIM>>>(Lam, logstep, Bmat, Cmat, Wenc, Wdec);

    // launch 3
    ln1_kernel<<<dim3(LDIM/16, BSZ), 256>>>(x, ln1g, ln1b, fxh, fxl);

    // launch 4 (ncu capture slot): Bu = fx @ Bbar^T -> fp16 [BL, 2P]
    mma_gemm<5><<<dim3(3, 512), 256, SMEM_GEMM>>>(fxh, wb, nullptr, CDIM,
                                                  buf, nullptr, nullptr, nullptr);

    // launch 5-6: scan
    scan_a<<<dim3(NCH, BSZ), PDIM>>>(buf, carry);
    scan_c<<<dim3(NCH, BSZ), PDIM>>>(buf, carry, buh);

    // launch 7: y = gelu(xs @ Ceff^T + D*fx) + fx
    mma_gemm<1><<<dim3(3, 512), 256, SMEM_GEMM>>>(buh, wc, y, CDIM,
                                                  nullptr, fxh, fxl, Dv);

    // launch 8
    ln2_kernel<<<BLTOK/8, 256>>>(y, ln2g, ln2b, fyh, fyl);

    // launch 9: gg = GEGLU(fy @ Wenc_interleaved^T) -> fp16 [BL, 384]
    mma_gemm<3><<<dim3(6, 512), 256, SMEM_GEMM>>>(fyh, we, nullptr, CDIM,
                                                  ggh, nullptr, nullptr, nullptr);

    // launch 10: out = transpose(gg @ Wdec^T + fy) -> [B,C,L]
    mma_gemm<4><<<dim3(3, 512), 256, SMEM_GEMM>>>(ggh, wd, out, CDIM,
                                                  nullptr, fyh, fyl, nullptr);
}

// round 9
// speedup vs baseline: 4.7497x; 1.0698x over previous
#include <cuda_runtime.h>
#include <cuda_fp16.h>
#include <math.h>
#include <stdint.h>

#define BSZ  16
#define CDIM 384
#define LDIM 4096
#define PDIM 192
#define BLTOK (BSZ*LDIM)      // 65536
#define NCH  64
#define TCH  64
#define KDIM 384

// ---------------- static scratch (no allocations allowed) ----------------
__device__ float g_y [(size_t)BLTOK*CDIM];
__device__ float g_lam [2*PDIM];
__device__ float g_lamT[2*PDIM];
__device__ float g_carry[(size_t)BSZ*NCH*CDIM];

// fp16 operands; lo-arrays only where an epilogue residual needs full accuracy
__device__ __half g_buf[(size_t)BLTOK*CDIM];   // Bu fp16 (pre-scan)
__device__ __half g_fxh[(size_t)BLTOK*CDIM], g_fxl[(size_t)BLTOK*CDIM];
__device__ __half g_buh[(size_t)BLTOK*CDIM];   // xs fp16 (post-scan)
__device__ __half g_fyh[(size_t)BLTOK*CDIM], g_fyl[(size_t)BLTOK*CDIM];
__device__ __half g_ggh[(size_t)BLTOK*CDIM];
__device__ __half g_wb[CDIM*CDIM];
__device__ __half g_wc[CDIM*CDIM];
__device__ __half g_we[2*CDIM*CDIM];   // interleaved z1/z2 rows
__device__ __half g_wd[CDIM*CDIM];

__device__ __forceinline__ float gelu_f(float v){
    return 0.5f*v*(1.0f + erff(v*0.70710678118654752f));
}
__device__ __forceinline__ void split_hl(float v, __half& h, __half& l){
    h = __float2half_rn(v);
    l = __float2half_rn(v - __half2float(h));
}
__device__ __forceinline__ uint32_t smem_u32(const void* p){
    uint32_t a;
    asm("{ .reg .u64 t; cvta.to.shared.u64 t, %1; cvt.u32.u64 %0, t; }" : "=r"(a) : "l"(p));
    return a;
}

// ---------------- MMA / ldmatrix / cp.async primitives (sm_80+ neutral PTX) ----------------
#define CP16(sa, ga)  asm volatile("cp.async.cg.shared.global [%0], [%1], 16;" :: "r"(sa), "l"(ga))
#define CPCOMMIT()    asm volatile("cp.async.commit_group;")
#define CPWAIT(n)     asm volatile("cp.async.wait_group %0;" :: "n"(n))

#define LDSM4(r, addr) asm volatile( \
    "ldmatrix.sync.aligned.m8n8.x4.shared.b16 {%0,%1,%2,%3}, [%4];" \
    : "=r"((r)[0]),"=r"((r)[1]),"=r"((r)[2]),"=r"((r)[3]) : "r"(addr))

#define MMA(d, a, b0v, b1v) asm volatile( \
    "mma.sync.aligned.m16n8k16.row.col.f32.f16.f16.f32 " \
    "{%0,%1,%2,%3},{%4,%5,%6,%7},{%8,%9},{%0,%1,%2,%3};" \
    : "+f"((d)[0]),"+f"((d)[1]),"+f"((d)[2]),"+f"((d)[3]) \
    : "r"((a)[0]),"r"((a)[1]),"r"((a)[2]),"r"((a)[3]),"r"(b0v),"r"(b1v))

// ============ fp16 single-pass NT GEMM: C[M,*] = A[M,384] @ B[*,384]^T ============
// tile 128x128, BK=64, 3-stage cp.async (1 sync/chunk, 6 chunks), warp grid 2x4 (64x32)
// stage layout: A @0 (128x144B), B @18432 ; stage stride 36864 ; rows padded to 144B
// EPI 1: f=e0h+e0l; v=acc+e1[n]*f; Cout=gelu(v)+f   (fp32)
// EPI 3: GEGLU pairs -> smem staged -> outH fp16 [BL, 384]
// EPI 4: f=e0h+e0l; o=acc+f; write Cout transposed [B,C,L] via smem staging
// EPI 5: plain fp16 out -> outH
template<int EPI>
__global__ __launch_bounds__(256,2) void mma_gemm(
    const __half* __restrict__ Ah,
    const __half* __restrict__ Bm,
    float* __restrict__ Cout, int Nout,
    __half* __restrict__ outH,
    const __half* __restrict__ e0h, const __half* __restrict__ e0l,
    const float* __restrict__ e1)
{
    extern __shared__ char smem[];
    uint32_t sb = smem_u32(smem);
    const int tid = threadIdx.x;
    const int bm = blockIdx.y*128, bn = blockIdx.x*128;

    // ---- load indexing: 128 rows x 8 segs of 16B per array; 4 row-groups/thread ----
    const int lr  = tid >> 3;          // row 0..31 (+32,64,96)
    const int seg = tid & 7;           // 16B segment within 128B row
    const __half* pa0 = Ah + (size_t)(bm+lr)*KDIM + seg*8;
    const __half* pb0 = Bm + (size_t)(bn+lr)*KDIM + seg*8;
    const uint32_t s0 = lr*144 + seg*16;

    // ---- compute indexing ----
    const int lane = tid & 31, w = tid >> 5;
    const int wm = (w >> 2)*64, wn = (w & 3)*32;
    const uint32_t aoff = (uint32_t)(wm + (lane & 15))*144 + (lane >> 4)*16;
    const int bg = lane >> 3, blg = lane & 7;
    const uint32_t boff = (uint32_t)(wn + (bg >> 1)*8 + blg)*144 + (bg & 1)*16;

    float acc[4][4][4];
    #pragma unroll
    for (int i=0;i<4;i++)
        #pragma unroll
        for (int j=0;j<4;j++)
            #pragma unroll
            for (int q=0;q<4;q++) acc[i][j][q]=0.f;

    auto issue = [&](int st, int kc){
        uint32_t sbase = sb + st*36864;
        #pragma unroll
        for (int h = 0; h < 4; h++){
            size_t rofs = (size_t)kc + (size_t)h*32*KDIM;
            uint32_t sa = sbase + s0 + h*32*144;
            CP16(sa,         pa0 + rofs);
            CP16(sa + 18432, pb0 + rofs);
        }
        CPCOMMIT();
    };

    issue(0, 0);
    issue(1, 64);
    int stg = 0;                        // stage of chunk c
    #pragma unroll 1
    for (int c = 0; c < 6; c++){
        if (c < 5) { CPWAIT(1); } else { CPWAIT(0); }
        __syncthreads();
        if (c + 2 < 6){
            int st2 = stg + 2; if (st2 >= 3) st2 -= 3;
            issue(st2, (c+2)*64);
        }
        uint32_t base = sb + stg*36864;
        #pragma unroll
        for (int ks = 0; ks < 4; ks++){
            uint32_t kb = ks*32;
            uint32_t a[4][4], bf[4][2], t[4];
            #pragma unroll
            for (int i=0;i<4;i++) LDSM4(a[i], base + aoff + i*16*144 + kb);
            #pragma unroll
            for (int jp=0;jp<2;jp++){
                LDSM4(t, base + 18432 + boff + jp*16*144 + kb);
                bf[2*jp][0]=t[0]; bf[2*jp][1]=t[1]; bf[2*jp+1][0]=t[2]; bf[2*jp+1][1]=t[3];
            }
            #pragma unroll
            for (int i=0;i<4;i++)
                #pragma unroll
                for (int j=0;j<4;j++) MMA(acc[i][j], a[i], bf[j][0], bf[j][1]);
        }
        if (++stg == 3) stg = 0;
    }

    // ---- epilogue ----
    const int r0 = lane >> 2, cc = (lane & 3)*2;
    if (EPI == 1){
        #pragma unroll
        for (int i=0;i<4;i++){
            int row = bm + wm + i*16 + r0;
            #pragma unroll
            for (int j=0;j<4;j++){
                int col = bn + wn + j*8 + cc;
                float v0 = acc[i][j][0], v1 = acc[i][j][1];
                float v2 = acc[i][j][2], v3 = acc[i][j][3];
                float2 d2 = *(const float2*)(e1 + col);
                __half2 h0 = *(const __half2*)(e0h + (size_t)row*CDIM + col);
                __half2 l0 = *(const __half2*)(e0l + (size_t)row*CDIM + col);
                __half2 h1 = *(const __half2*)(e0h + (size_t)(row+8)*CDIM + col);
                __half2 l1 = *(const __half2*)(e0l + (size_t)(row+8)*CDIM + col);
                float f0x = __half2float(h0.x) + __half2float(l0.x);
                float f0y = __half2float(h0.y) + __half2float(l0.y);
                float f1x = __half2float(h1.x) + __half2float(l1.x);
                float f1y = __half2float(h1.y) + __half2float(l1.y);
                v0 = gelu_f(v0 + d2.x*f0x) + f0x;
                v1 = gelu_f(v1 + d2.y*f0y) + f0y;
                v2 = gelu_f(v2 + d2.x*f1x) + f1x;
                v3 = gelu_f(v3 + d2.y*f1y) + f1y;
                *(float2*)(Cout + (size_t)row*Nout + col)     = make_float2(v0, v1);
                *(float2*)(Cout + (size_t)(row+8)*Nout + col) = make_float2(v2, v3);
            }
        }
    } else if (EPI == 3){
        // GEGLU: even col = z1, odd col = z2 (interleaved W_enc); stage hi in smem
        __half* sth = (__half*)smem;    // [128 rows][72 halves stride]
        __syncthreads();
        #pragma unroll
        for (int i=0;i<4;i++){
            int rl = wm + i*16 + r0;
            #pragma unroll
            for (int j=0;j<4;j++){
                int gcl = (wn >> 1) + j*4 + (lane & 3);
                float g0 = acc[i][j][0] * gelu_f(acc[i][j][1]);
                float g1 = acc[i][j][2] * gelu_f(acc[i][j][3]);
                sth[rl*72 + gcl]     = __float2half_rn(g0);
                sth[(rl+8)*72 + gcl] = __float2half_rn(g1);
            }
        }
        __syncthreads();
        int gcol0 = bn >> 1;
        #pragma unroll
        for (int q = 0; q < 16; q++){
            int rl = w*16 + q;
            uint32_t v = *(const uint32_t*)(sth + rl*72 + 2*lane);
            *(uint32_t*)(outH + (size_t)(bm + rl)*CDIM + gcol0 + 2*lane) = v;
        }
    } else if (EPI == 4){
        // residual add then transposed store to [B, C, L] via smem staging
        float* smf = (float*)smem;      // [128 cols][132 row-stride]
        __syncthreads();
        #pragma unroll
        for (int i=0;i<4;i++){
            int row = bm + wm + i*16 + r0;
            int rl  = wm + i*16 + r0;
            #pragma unroll
            for (int j=0;j<4;j++){
                int col = bn + wn + j*8 + cc;
                int clo = wn + j*8 + cc;
                __half2 h0 = *(const __half2*)(e0h + (size_t)row*CDIM + col);
                __half2 l0 = *(const __half2*)(e0l + (size_t)row*CDIM + col);
                __half2 h1 = *(const __half2*)(e0h + (size_t)(row+8)*CDIM + col);
                __half2 l1 = *(const __half2*)(e0l + (size_t)(row+8)*CDIM + col);
                smf[(clo  )*132 + rl    ] = acc[i][j][0] + __half2float(h0.x) + __half2float(l0.x);
                smf[(clo+1)*132 + rl    ] = acc[i][j][1] + __half2float(h0.y) + __half2float(l0.y);
                smf[(clo  )*132 + rl + 8] = acc[i][j][2] + __half2float(h1.x) + __half2float(l1.x);
                smf[(clo+1)*132 + rl + 8] = acc[i][j][3] + __half2float(h1.y) + __half2float(l1.y);
            }
        }
        __syncthreads();
        int b  = bm >> 12;
        int l0 = bm & 4095;
        #pragma unroll
        for (int q = 0; q < 16; q++){
            int cl = w*16 + q;
            float4 v = *(const float4*)(smf + cl*132 + lane*4);
            *(float4*)(Cout + ((size_t)b*CDIM + bn + cl)*LDIM + l0 + lane*4) = v;
        }
    } else {
        // EPI 5: plain fp16 store
        #pragma unroll
        for (int i=0;i<4;i++){
            int row = bm + wm + i*16 + r0;
            #pragma unroll
            for (int j=0;j<4;j++){
                int col = bn + wn + j*8 + cc;
                __half2 v01 = __floats2half2_rn(acc[i][j][0], acc[i][j][1]);
                __half2 v23 = __floats2half2_rn(acc[i][j][2], acc[i][j][3]);
                *(__half2*)(outH + (size_t)row*Nout + col)     = v01;
                *(__half2*)(outH + (size_t)(row+8)*Nout + col) = v23;
            }
        }
    }
}

// ---------------- prep: discretization (must run first; others read g_lam) ----------------
__global__ void prep_lam(const float* __restrict__ Lam, const float* __restrict__ logstep){
    int p = threadIdx.x;
    float step = expf(logstep[p]);
    float lre = Lam[2*p], lim = Lam[2*p+1];
    double a  = exp((double)lre*(double)step);
    double th = (double)lim*(double)step;
    g_lam[2*p]   = (float)(a*cos(th));
    g_lam[2*p+1] = (float)(a*sin(th));
    double aT  = exp((double)TCH*(double)lre*(double)step);
    double thT = (double)TCH*th;
    g_lamT[2*p]   = (float)(aT*cos(thT));
    g_lamT[2*p+1] = (float)(aT*sin(thT));
}

// one kernel for all weight preps: wb(192) | wc(384) | we(768) | wd(384) blocks
__global__ void prep_all(const float* __restrict__ Lam, const float* __restrict__ logstep,
                         const float* __restrict__ Bmat, const float* __restrict__ Cmat,
                         const float* __restrict__ Wenc, const float* __restrict__ Wdec){
    int bid = blockIdx.x, tid = threadIdx.x;
    if (bid < 192){
        int p = bid, c = tid;
        float lre = Lam[2*p], lim = Lam[2*p+1];
        float lbr = g_lam[2*p], lbi = g_lam[2*p+1];
        float den = lre*lre + lim*lim;
        float cr = ((lbr-1.0f)*lre + lbi*lim)/den;
        float ci = (lbi*lre - (lbr-1.0f)*lim)/den;
        float br = Bmat[(p*CDIM + c)*2], bi = Bmat[(p*CDIM + c)*2 + 1];
        g_wb[(size_t)p*CDIM + c]        = __float2half_rn(cr*br - ci*bi);
        g_wb[(size_t)(PDIM+p)*CDIM + c] = __float2half_rn(cr*bi + ci*br);
    } else if (bid < 576){
        if (tid < PDIM){
            int hrow = bid - 192, p = tid;
            float step = expf(logstep[p]);
            float lim = Lam[2*p+1];
            float freq = step*fabsf(lim)*(float)(1.0/(2.0*3.14159265358979323846));
            float m = (freq < 0.25f) ? 2.0f : 0.0f;
            float cre = Cmat[(hrow*PDIM + p)*2], cim = Cmat[(hrow*PDIM + p)*2 + 1];
            g_wc[(size_t)hrow*CDIM + p]        = __float2half_rn( m*cre);
            g_wc[(size_t)hrow*CDIM + PDIM + p] = __float2half_rn(-m*cim);
        }
    } else if (bid < 1344){
        int n = bid - 576, c = tid;
        int src = (n & 1) ? (CDIM + (n >> 1)) : (n >> 1);
        g_we[(size_t)n*CDIM + c] = __float2half_rn(Wenc[(size_t)src*CDIM + c]);
    } else {
        int i = (bid - 1344)*CDIM + tid;   // 384 blocks x 384 = 147456 exactly
        g_wd[i] = __float2half_rn(Wdec[i]);
    }
}

// ---------------- LayerNorm 1 : x[B,C,L] -> hi/lo fp16 [BL,C] ----------------
__global__ __launch_bounds__(256) void ln1_kernel(const float* __restrict__ x,
                                                  const float* __restrict__ gam,
                                                  const float* __restrict__ bet,
                                                  __half* __restrict__ fxh,
                                                  __half* __restrict__ fxl){
    __shared__ float tile[CDIM][17];
    int b = blockIdx.y, l0 = blockIdx.x*16;
    int tid = threadIdx.x;
    for (int idx = tid; idx < CDIM*16; idx += 256){
        int c = idx >> 4, j = idx & 15;
        tile[c][j] = x[((size_t)b*CDIM + c)*LDIM + l0 + j];
    }
    __syncthreads();
    int w = tid >> 5, lane = tid & 31;
    for (int j = w*2; j < w*2 + 2; j++){
        float v[12]; float s = 0.0f;
        #pragma unroll
        for (int k = 0; k < 12; k++){ v[k] = tile[lane + 32*k][j]; s += v[k]; }
        #pragma unroll
        for (int o = 16; o; o >>= 1) s += __shfl_xor_sync(0xffffffffu, s, o);
        float mu = s * (1.0f/CDIM);
        float q = 0.0f;
        #pragma unroll
        for (int k = 0; k < 12; k++){ float d = v[k]-mu; q += d*d; }
        #pragma unroll
        for (int o = 16; o; o >>= 1) q += __shfl_xor_sync(0xffffffffu, q, o);
        float inv = rsqrtf(q*(1.0f/CDIM) + 1e-5f);
        size_t row = ((size_t)b*LDIM + l0 + j)*CDIM;
        #pragma unroll
        for (int k = 0; k < 12; k++){
            int c = lane + 32*k;
            float val = (v[k]-mu)*inv*gam[c] + bet[c];
            __half h,l; split_hl(val,h,l);
            fxh[row + c] = h; fxl[row + c] = l;
        }
    }
}

// ---------------- LayerNorm 2 : y[BL,C] -> hi/lo ----------------
__global__ __launch_bounds__(256) void ln2_kernel(const float* __restrict__ y,
                                                  const float* __restrict__ gam,
                                                  const float* __restrict__ bet,
                                                  __half* __restrict__ fyh,
                                                  __half* __restrict__ fyl){
    int row = blockIdx.x*8 + (threadIdx.x >> 5);
    int lane = threadIdx.x & 31;
    const float4* r4 = (const float4*)(y + (size_t)row*CDIM);
    float4 v[3]; float s = 0.0f;
    #pragma unroll
    for (int k = 0; k < 3; k++){ v[k] = r4[lane + 32*k]; s += v[k].x+v[k].y+v[k].z+v[k].w; }
    #pragma unroll
    for (int o = 16; o; o >>= 1) s += __shfl_xor_sync(0xffffffffu, s, o);
    float mu = s * (1.0f/CDIM);
    float q = 0.0f;
    #pragma unroll
    for (int k = 0; k < 3; k++){
        float dx=v[k].x-mu, dy=v[k].y-mu, dz=v[k].z-mu, dw=v[k].w-mu;
        q += dx*dx+dy*dy+dz*dz+dw*dw;
    }
    #pragma unroll
    for (int o = 16; o; o >>= 1) q += __shfl_xor_sync(0xffffffffu, q, o);
    float inv = rsqrtf(q*(1.0f/CDIM) + 1e-5f);
    #pragma unroll
    for (int k = 0; k < 3; k++){
        int c4 = lane + 32*k;
        float4 gg = ((const float4*)gam)[c4], bb = ((const float4*)bet)[c4];
        float rx = (v[k].x-mu)*inv*gg.x + bb.x;
        float ry = (v[k].y-mu)*inv*gg.y + bb.y;
        float rz = (v[k].z-mu)*inv*gg.z + bb.z;
        float rw = (v[k].w-mu)*inv*gg.w + bb.w;
        size_t base = (size_t)row*CDIM + c4*4;
        __half h,l;
        split_hl(rx,h,l); fyh[base+0]=h; fyl[base+0]=l;
        split_hl(ry,h,l); fyh[base+1]=h; fyl[base+1]=l;
        split_hl(rz,h,l); fyh[base+2]=h; fyl[base+2]=l;
        split_hl(rw,h,l); fyh[base+3]=h; fyl[base+3]=l;
    }
}

// ---------------- chunked constant-coefficient complex scan (fp16 Bu) ----------------
__global__ void scan_a(const __half* __restrict__ bu, float* __restrict__ carry){
    int p = threadIdx.x, ch = blockIdx.x, b = blockIdx.y;
    float lre = g_lam[2*p], lim = g_lam[2*p+1];
    float sre = 0.0f, sim = 0.0f;
    size_t base = ((size_t)b*LDIM + (size_t)ch*TCH)*CDIM;
    for (int i = 0; i < TCH; i++){
        size_t idx = base + (size_t)i*CDIM;
        float br = __half2float(bu[idx+p]), bi = __half2float(bu[idx+PDIM+p]);
        float nr = fmaf(lre, sre, fmaf(-lim, sim, br));
        float ni = fmaf(lre, sim, fmaf( lim, sre, bi));
        sre = nr; sim = ni;
    }
    size_t cidx = ((size_t)b*NCH + ch)*CDIM;
    carry[cidx+p] = sre; carry[cidx+PDIM+p] = sim;
}

// scan_c: compose prefix from raw carries (scan_b folded in), run local recurrence, emit fp16
__global__ void scan_c(const __half* __restrict__ bu, const float* __restrict__ carry,
                       __half* __restrict__ bh){
    int p = threadIdx.x, ch = blockIdx.x, b = blockIdx.y;
    float tr = g_lamT[2*p], ti = g_lamT[2*p+1];
    float sre = 0.0f, sim = 0.0f;
    for (int k = 0; k < ch; k++){
        size_t ci = ((size_t)b*NCH + k)*CDIM;
        float cr = carry[ci+p], cm = carry[ci+PDIM+p];
        float nr = fmaf(tr, sre, fmaf(-ti, sim, cr));
        float ni = fmaf(tr, sim, fmaf( ti, sre, cm));
        sre = nr; sim = ni;
    }
    float lre = g_lam[2*p], lim = g_lam[2*p+1];
    size_t base = ((size_t)b*LDIM + (size_t)ch*TCH)*CDIM;
    for (int i = 0; i < TCH; i++){
        size_t idx = base + (size_t)i*CDIM;
        float br = __half2float(bu[idx+p]), bi = __half2float(bu[idx+PDIM+p]);
        float nr = fmaf(lre, sre, fmaf(-lim, sim, br));
        float ni = fmaf(lre, sim, fmaf( lim, sre, bi));
        sre = nr; sim = ni;
        bh[idx+p]      = __float2half_rn(nr);
        bh[idx+PDIM+p] = __float2half_rn(ni);
    }
}

// ---------------- launch ----------------
extern "C" void kernel_launch(void* const* d_in, const int* in_sizes, int n_in,
                              void* d_out, int out_size){
    const float* x       = (const float*)d_in[0];
    const float* ln1g    = (const float*)d_in[1];
    const float* ln1b    = (const float*)d_in[2];
    const float* Lam     = (const float*)d_in[3];
    const float* Bmat    = (const float*)d_in[4];
    const float* Cmat    = (const float*)d_in[5];
    const float* Dv      = (const float*)d_in[6];
    const float* logstep = (const float*)d_in[7];
    const float* ln2g    = (const float*)d_in[8];
    const float* ln2b    = (const float*)d_in[9];
    const float* Wenc    = (const float*)d_in[10];
    const float* Wdec    = (const float*)d_in[11];
    float* out = (float*)d_out;

    float *y,*carry;
    cudaGetSymbolAddress((void**)&y,     g_y);
    cudaGetSymbolAddress((void**)&carry, g_carry);

    __half *buf,*fxh,*fxl,*buh,*fyh,*fyl,*ggh,*wb,*wc,*we,*wd;
    cudaGetSymbolAddress((void**)&buf, g_buf);
    cudaGetSymbolAddress((void**)&fxh, g_fxh); cudaGetSymbolAddress((void**)&fxl, g_fxl);
    cudaGetSymbolAddress((void**)&buh, g_buh);
    cudaGetSymbolAddress((void**)&fyh, g_fyh); cudaGetSymbolAddress((void**)&fyl, g_fyl);
    cudaGetSymbolAddress((void**)&ggh, g_ggh);
    cudaGetSymbolAddress((void**)&wb,  g_wb);  cudaGetSymbolAddress((void**)&wc,  g_wc);
    cudaGetSymbolAddress((void**)&we,  g_we);  cudaGetSymbolAddress((void**)&wd,  g_wd);

    const int SMEM_GEMM = 3*36864;   // 110592 B (3-stage BK=64; covers EPI staging)
    cudaFuncSetAttribute(mma_gemm<1>, cudaFuncAttributeMaxDynamicSharedMemorySize, SMEM_GEMM);
    cudaFuncSetAttribute(mma_gemm<3>, cudaFuncAttributeMaxDynamicSharedMemorySize, SMEM_GEMM);
    cudaFuncSetAttribute(mma_gemm<4>, cudaFuncAttributeMaxDynamicSharedMemorySize, SMEM_GEMM);
    cudaFuncSetAttribute(mma_gemm<5>, cudaFuncAttributeMaxDynamicSharedMemorySize, SMEM_GEMM);

    // launch 1-2: prep
    prep_lam<<<1, PDIM>>>(Lam, logstep);
    prep_all<<<1728, CDIM>>>(Lam, logstep, Bmat, Cmat, Wenc, Wdec);

    // launch 3
    ln1_kernel<<<dim3(LDIM/16, BSZ), 256>>>(x, ln1g, ln1b, fxh, fxl);

    // launch 4 (ncu capture slot): Bu = fx @ Bbar^T -> fp16 [BL, 2P]
    mma_gemm<5><<<dim3(3, 512), 256, SMEM_GEMM>>>(fxh, wb, nullptr, CDIM,
                                                  buf, nullptr, nullptr, nullptr);

    // launch 5-6: scan
    scan_a<<<dim3(NCH, BSZ), PDIM>>>(buf, carry);
    scan_c<<<dim3(NCH, BSZ), PDIM>>>(buf, carry, buh);

    // launch 7: y = gelu(xs @ Ceff^T + D*fx) + fx
    mma_gemm<1><<<dim3(3, 512), 256, SMEM_GEMM>>>(buh, wc, y, CDIM,
                                                  nullptr, fxh, fxl, Dv);

    // launch 8
    ln2_kernel<<<BLTOK/8, 256>>>(y, ln2g, ln2b, fyh, fyl);

    // launch 9: gg = GEGLU(fy @ Wenc_interleaved^T) -> fp16 [BL, 384]
    mma_gemm<3><<<dim3(6, 512), 256, SMEM_GEMM>>>(fyh, we, nullptr, CDIM,
                                                  ggh, nullptr, nullptr, nullptr);

    // launch 10: out = transpose(gg @ Wdec^T + fy) -> [B,C,L]
    mma_gemm<4><<<dim3(3, 512), 256, SMEM_GEMM>>>(ggh, wd, out, CDIM,
                                                  nullptr, fyh, fyl, nullptr);
}